// round 1
// baseline (speedup 1.0000x reference)
#include <cuda_runtime.h>
#include <math.h>

// ---------------- problem constants ----------------
#define BATCH 8
#define NTOK  16384
#define MTOT  (BATCH * NTOK)      // 131072 tokens
#define IDIM  512
#define DDIM  256
#define EMB   8
#define NC    11                  // C+1 clusters
#define NSEG  (BATCH * NC)        // 88

// ---------------- scratch (device globals; no allocations allowed) ----------------
__device__ float g_X[(size_t)MTOT * IDIM];        // fused features, 256 MB
__device__ float g_Apart[8 * MTOT];               // per-colblock partial attention logits
__device__ float g_A[MTOT];
__device__ float g_w[MTOT];
__device__ float g_segmax[NSEG];
__device__ float g_segdenom[NSEG];
__device__ int   g_present[NSEG];
__device__ float g_cfeatPart[BATCH * 16 * NC * IDIM];  // 16 token-chunks per batch
__device__ float g_cfeat[NSEG * IDIM];
__device__ float g_cf2[NSEG * IDIM];
__device__ float g_A2[NSEG];

__device__ __forceinline__ int clip_cid(int c) { return c < 0 ? 0 : (c > 10 ? 10 : c); }

// =====================================================================
// Kernel 1: X = relu([h, emb[cid]] @ W_fuse + b_fuse)
// 128x64 tile, BK=16, 256 threads, 8x4 per-thread microtile.
// Embedding contribution (K rows 512..519) folded into the epilogue.
// =====================================================================
__global__ __launch_bounds__(256) void k_fuse(
    const float* __restrict__ h, const int* __restrict__ cids,
    const float* __restrict__ emb, const float* __restrict__ Wf,
    const float* __restrict__ bfu)
{
    __shared__ float As[16][132];   // transposed A tile (pad to dodge conflicts)
    __shared__ float Bs[16][64];
    __shared__ float sWt[8][64];    // W_fuse rows 512..519, this block's cols
    __shared__ float sB[64];

    const int tid = threadIdx.x;
    const int colBase = blockIdx.x * 64;
    const int rowBase = blockIdx.y * 128;

    for (int i = tid; i < 8 * 64; i += 256) {
        int e = i >> 6, n = i & 63;
        sWt[e][n] = Wf[(512 + e) * 512 + colBase + n];
    }
    if (tid < 64) sB[tid] = bfu[colBase + tid];

    const int tx = tid & 15, ty = tid >> 4;
    const int ar = tid >> 2, af = tid & 3;   // A-tile loader: row, float4-idx
    const int br = tid >> 4, bq = tid & 15;  // B-tile loader: row, float4-idx

    float acc[8][4];
#pragma unroll
    for (int i = 0; i < 8; i++)
#pragma unroll
        for (int j = 0; j < 4; j++) acc[i][j] = 0.0f;

    for (int k0 = 0; k0 < 512; k0 += 16) {
        float4 va0 = *(const float4*)&h[(size_t)(rowBase + ar) * 512 + k0 + af * 4];
        float4 va1 = *(const float4*)&h[(size_t)(rowBase + ar + 64) * 512 + k0 + af * 4];
        float4 vb  = *(const float4*)&Wf[(size_t)(k0 + br) * 512 + colBase + bq * 4];
        __syncthreads();
        As[af * 4 + 0][ar] = va0.x; As[af * 4 + 1][ar] = va0.y;
        As[af * 4 + 2][ar] = va0.z; As[af * 4 + 3][ar] = va0.w;
        As[af * 4 + 0][ar + 64] = va1.x; As[af * 4 + 1][ar + 64] = va1.y;
        As[af * 4 + 2][ar + 64] = va1.z; As[af * 4 + 3][ar + 64] = va1.w;
        *(float4*)&Bs[br][bq * 4] = vb;
        __syncthreads();
#pragma unroll
        for (int k = 0; k < 16; k++) {
            float4 a0 = *(const float4*)&As[k][ty * 8];
            float4 a1 = *(const float4*)&As[k][ty * 8 + 4];
            float4 bv = *(const float4*)&Bs[k][tx * 4];
            float av[8] = {a0.x, a0.y, a0.z, a0.w, a1.x, a1.y, a1.z, a1.w};
            float bw[4] = {bv.x, bv.y, bv.z, bv.w};
#pragma unroll
            for (int i = 0; i < 8; i++)
#pragma unroll
                for (int j = 0; j < 4; j++) acc[i][j] = fmaf(av[i], bw[j], acc[i][j]);
        }
    }

#pragma unroll
    for (int i = 0; i < 8; i++) {
        int row = rowBase + ty * 8 + i;
        int cid = clip_cid(cids[row]);
        float4 e0 = *(const float4*)&emb[cid * 8];
        float4 e1 = *(const float4*)&emb[cid * 8 + 4];
        float ev[8] = {e0.x, e0.y, e0.z, e0.w, e1.x, e1.y, e1.z, e1.w};
        float4 outv;
        float* po = &outv.x;
#pragma unroll
        for (int j = 0; j < 4; j++) {
            int col = tx * 4 + j;
            float v = acc[i][j] + sB[col];
#pragma unroll
            for (int e = 0; e < 8; e++) v = fmaf(ev[e], sWt[e][col], v);
            po[j] = fmaxf(v, 0.0f);
        }
        *(float4*)&g_X[(size_t)row * 512 + colBase + tx * 4] = outv;
    }
}

// =====================================================================
// Kernel 2: dual GEMM  a=tanh(X@Wa1+ba1), g=sigmoid(X@Wb1+bb1),
//           partial_A[row] += sum_cols (a*g)*Wc1[col]   (deterministic partials)
// 128x32 tile over N=256 (8 col blocks), BK=16, 256 threads, 8x2 x2 microtile.
// =====================================================================
__global__ __launch_bounds__(256) void k_gate1(
    const float* __restrict__ Wa1, const float* __restrict__ ba1,
    const float* __restrict__ Wb1, const float* __restrict__ bb1,
    const float* __restrict__ Wc1)
{
    __shared__ float As[16][132];
    __shared__ float Ba[16][32];
    __shared__ float Bg[16][32];
    __shared__ float sba[32], sbg[32], sWc[32];
    __shared__ float sred[128][17];

    const int tid = threadIdx.x;
    const int colBase = blockIdx.x * 32;
    const int rowBase = blockIdx.y * 128;

    if (tid < 32) {
        sba[tid] = ba1[colBase + tid];
        sbg[tid] = bb1[colBase + tid];
        sWc[tid] = Wc1[colBase + tid];
    }

    const int tx = tid & 15, ty = tid >> 4;
    const int ar = tid >> 2, af = tid & 3;
    const int lid = tid & 127;
    const int br = lid >> 3, bq = lid & 7;

    float accA[8][2], accG[8][2];
#pragma unroll
    for (int i = 0; i < 8; i++) { accA[i][0] = accA[i][1] = accG[i][0] = accG[i][1] = 0.0f; }

    for (int k0 = 0; k0 < 512; k0 += 16) {
        float4 va0 = *(const float4*)&g_X[(size_t)(rowBase + ar) * 512 + k0 + af * 4];
        float4 va1 = *(const float4*)&g_X[(size_t)(rowBase + ar + 64) * 512 + k0 + af * 4];
        const float* wsrc = (tid < 128) ? Wa1 : Wb1;
        float4 vb = *(const float4*)&wsrc[(size_t)(k0 + br) * 256 + colBase + bq * 4];
        __syncthreads();
        As[af * 4 + 0][ar] = va0.x; As[af * 4 + 1][ar] = va0.y;
        As[af * 4 + 2][ar] = va0.z; As[af * 4 + 3][ar] = va0.w;
        As[af * 4 + 0][ar + 64] = va1.x; As[af * 4 + 1][ar + 64] = va1.y;
        As[af * 4 + 2][ar + 64] = va1.z; As[af * 4 + 3][ar + 64] = va1.w;
        if (tid < 128) *(float4*)&Ba[br][bq * 4] = vb;
        else           *(float4*)&Bg[br][bq * 4] = vb;
        __syncthreads();
#pragma unroll
        for (int k = 0; k < 16; k++) {
            float4 a0 = *(const float4*)&As[k][ty * 8];
            float4 a1 = *(const float4*)&As[k][ty * 8 + 4];
            float av[8] = {a0.x, a0.y, a0.z, a0.w, a1.x, a1.y, a1.z, a1.w};
            float2 bva = *(const float2*)&Ba[k][tx * 2];
            float2 bvg = *(const float2*)&Bg[k][tx * 2];
#pragma unroll
            for (int i = 0; i < 8; i++) {
                accA[i][0] = fmaf(av[i], bva.x, accA[i][0]);
                accA[i][1] = fmaf(av[i], bva.y, accA[i][1]);
                accG[i][0] = fmaf(av[i], bvg.x, accG[i][0]);
                accG[i][1] = fmaf(av[i], bvg.y, accG[i][1]);
            }
        }
    }

    // epilogue: gated product dotted with Wc1 slice -> per-row partial
#pragma unroll
    for (int i = 0; i < 8; i++) {
        float p = 0.0f;
#pragma unroll
        for (int j = 0; j < 2; j++) {
            int col = tx * 2 + j;
            float a = tanhf(accA[i][j] + sba[col]);
            float gg = 1.0f / (1.0f + expf(-(accG[i][j] + sbg[col])));
            p = fmaf(a * gg, sWc[col], p);
        }
        sred[ty * 8 + i][tx] = p;
    }
    __syncthreads();
    if (tid < 128) {
        float s = 0.0f;
#pragma unroll
        for (int j = 0; j < 16; j++) s += sred[tid][j];
        g_Apart[blockIdx.x * MTOT + rowBase + tid] = s;
    }
}

__global__ void k_reduceA() {
    int t = blockIdx.x * blockDim.x + threadIdx.x;
    if (t >= MTOT) return;
    float s = 0.0f;
#pragma unroll
    for (int j = 0; j < 8; j++) s += g_Apart[j * MTOT + t];
    g_A[t] = s;
}

// =====================================================================
// Kernel 3: per-(batch,cluster) segment max / exp-sum / presence
// =====================================================================
__global__ __launch_bounds__(256) void k_segstat(const int* __restrict__ cids) {
    __shared__ float red[NC][256];
    __shared__ int   redc[NC][256];
    __shared__ float fmaxs[NC];
    const int b = blockIdx.x, tid = threadIdx.x;

    float lmax[NC]; int lc[NC];
#pragma unroll
    for (int c = 0; c < NC; c++) { lmax[c] = -3.0e38f; lc[c] = 0; }
    for (int t = tid; t < NTOK; t += 256) {
        int c = clip_cid(cids[b * NTOK + t]);
        float v = g_A[b * NTOK + t];
        if (v > lmax[c]) lmax[c] = v;
        lc[c]++;
    }
    for (int c = 0; c < NC; c++) { red[c][tid] = lmax[c]; redc[c][tid] = lc[c]; }
    __syncthreads();
    if (tid < NC) {
        float m = -3.0e38f; int cnt = 0;
        for (int i = 0; i < 256; i++) { m = fmaxf(m, red[tid][i]); cnt += redc[tid][i]; }
        float mm = (cnt > 0) ? m : 0.0f;
        fmaxs[tid] = mm;
        g_segmax[b * NC + tid] = mm;
        g_present[b * NC + tid] = (cnt > 0) ? 1 : 0;
    }
    __syncthreads();
    float ls[NC];
#pragma unroll
    for (int c = 0; c < NC; c++) ls[c] = 0.0f;
    for (int t = tid; t < NTOK; t += 256) {
        int c = clip_cid(cids[b * NTOK + t]);
        ls[c] += expf(g_A[b * NTOK + t] - fmaxs[c]);
    }
    for (int c = 0; c < NC; c++) red[c][tid] = ls[c];
    __syncthreads();
    if (tid < NC) {
        float s = 0.0f;
        for (int i = 0; i < 256; i++) s += red[tid][i];
        g_segdenom[b * NC + tid] = s;
    }
}

__global__ void k_w(const int* __restrict__ cids) {
    int t = blockIdx.x * blockDim.x + threadIdx.x;
    if (t >= MTOT) return;
    int b = t >> 14;
    int c = clip_cid(cids[t]);
    g_w[t] = expf(g_A[t] - g_segmax[b * NC + c]) / g_segdenom[b * NC + c];
}

// =====================================================================
// Kernel 4: segment-sum of w-weighted X, deterministic (chunk partials)
// grid (16 chunks, 8 batches), 512 threads (thread == feature)
// =====================================================================
__global__ __launch_bounds__(512) void k_accum(const int* __restrict__ cids) {
    __shared__ float acc[NC * 512];
    const int chunk = blockIdx.x, b = blockIdx.y, tid = threadIdx.x;
    for (int i = tid; i < NC * 512; i += 512) acc[i] = 0.0f;
    __syncthreads();
    const int base = b * NTOK + chunk * 1024;
    for (int it = 0; it < 1024; it++) {
        int row = base + it;
        int c = clip_cid(cids[row]);
        float wv = g_w[row];
        float x = g_X[(size_t)row * 512 + tid];
        acc[c * 512 + tid] += x * wv;
    }
    __syncthreads();
    float* dst = &g_cfeatPart[(size_t)(b * 16 + chunk) * NC * 512];
    for (int c = 0; c < NC; c++) dst[c * 512 + tid] = acc[c * 512 + tid];
}

__global__ void k_reduceC() {
    int idx = blockIdx.x * blockDim.x + threadIdx.x;
    if (idx >= NSEG * 512) return;
    int b = idx / (NC * 512);
    int off = idx % (NC * 512);
    float s = 0.0f;
#pragma unroll
    for (int j = 0; j < 16; j++) s += g_cfeatPart[(size_t)(b * 16 + j) * NC * 512 + off];
    g_cfeat[idx] = s;
}

// =====================================================================
// Kernel 5: per-cluster-row MLP + gated attention-2 logit (88 rows)
// =====================================================================
__global__ __launch_bounds__(512) void k_intra(
    const float* __restrict__ Wi, const float* __restrict__ bi,
    const float* __restrict__ Wa2, const float* __restrict__ ba2,
    const float* __restrict__ Wb2, const float* __restrict__ bb2,
    const float* __restrict__ Wc2)
{
    __shared__ float cfr[512];
    __shared__ float cf2s[512];
    __shared__ float red[256];
    const int row = blockIdx.x, tid = threadIdx.x;

    cfr[tid] = g_cfeat[row * 512 + tid];
    __syncthreads();
    float s = bi[tid];
    for (int k = 0; k < 512; k++) s = fmaf(cfr[k], Wi[k * 512 + tid], s);
    s = fmaxf(s, 0.0f);
    cf2s[tid] = s;
    g_cf2[row * 512 + tid] = s;
    __syncthreads();
    if (tid < 256) {
        float sa = ba2[tid], sg = bb2[tid];
        for (int k = 0; k < 512; k++) {
            float v = cf2s[k];
            sa = fmaf(v, Wa2[k * 256 + tid], sa);
            sg = fmaf(v, Wb2[k * 256 + tid], sg);
        }
        float a = tanhf(sa);
        float gg = 1.0f / (1.0f + expf(-sg));
        red[tid] = a * gg * Wc2[tid];
    }
    __syncthreads();
    for (int sft = 128; sft > 0; sft >>= 1) {
        if (tid < sft && tid + sft < 256) red[tid] += red[tid + sft];
        __syncthreads();
    }
    if (tid == 0) g_A2[row] = red[0];
}

// =====================================================================
// Kernel 6: per-batch masked softmax over clusters, slide pooling, head MLP
// =====================================================================
__global__ __launch_bounds__(512) void k_final(
    const float* __restrict__ Wint, const float* __restrict__ bint,
    const float* __restrict__ Wcls, const float* __restrict__ bcls,
    float* __restrict__ out)
{
    __shared__ float Wsm[NC];
    __shared__ float slide[512];
    __shared__ float inter[256];
    const int b = blockIdx.x, tid = threadIdx.x;

    if (tid == 0) {
        float av[NC];
        float m = -3.0e38f;
        for (int c = 0; c < NC; c++) {
            av[c] = g_present[b * NC + c] ? g_A2[b * NC + c] : -3.0e38f;
            m = fmaxf(m, av[c]);
        }
        float sden = 0.0f;
        float ex[NC];
        for (int c = 0; c < NC; c++) { ex[c] = expf(av[c] - m); sden += ex[c]; }
        for (int c = 0; c < NC; c++) Wsm[c] = ex[c] / sden;
    }
    __syncthreads();
    float sv = 0.0f;
    for (int c = 0; c < NC; c++) sv = fmaf(Wsm[c], g_cf2[(b * NC + c) * 512 + tid], sv);
    slide[tid] = sv;
    __syncthreads();
    if (tid < 256) {
        float v = bint[tid];
        for (int k = 0; k < 512; k++) v = fmaf(slide[k], Wint[k * 256 + tid], v);
        inter[tid] = fmaxf(v, 0.0f);
    }
    __syncthreads();
    if (tid < 2) {
        float o = bcls[tid];
        for (int k = 0; k < 256; k++) o = fmaf(inter[k], Wcls[k * 2 + tid], o);
        out[b * 2 + tid] = o;
    }
}

// =====================================================================
extern "C" void kernel_launch(void* const* d_in, const int* in_sizes, int n_in,
                              void* d_out, int out_size)
{
    const float* h    = (const float*)d_in[0];
    const int*   cids = (const int*)  d_in[1];
    const float* emb  = (const float*)d_in[2];
    const float* Wf   = (const float*)d_in[3];
    const float* bfu  = (const float*)d_in[4];
    const float* Wa1  = (const float*)d_in[5];
    const float* ba1  = (const float*)d_in[6];
    const float* Wb1  = (const float*)d_in[7];
    const float* bb1  = (const float*)d_in[8];
    const float* Wc1  = (const float*)d_in[9];
    // d_in[10] = bc1: constant shift inside segment softmax -> cancels exactly
    const float* Wi   = (const float*)d_in[11];
    const float* bi   = (const float*)d_in[12];
    const float* Wa2  = (const float*)d_in[13];
    const float* ba2  = (const float*)d_in[14];
    const float* Wb2  = (const float*)d_in[15];
    const float* bb2  = (const float*)d_in[16];
    const float* Wc2  = (const float*)d_in[17];
    // d_in[18] = bc2: cancels in inter-cluster softmax
    const float* Wint = (const float*)d_in[19];
    const float* bint = (const float*)d_in[20];
    const float* Wcls = (const float*)d_in[21];
    const float* bcls = (const float*)d_in[22];
    float* out = (float*)d_out;

    k_fuse  <<<dim3(8, 1024), 256>>>(h, cids, emb, Wf, bfu);
    k_gate1 <<<dim3(8, 1024), 256>>>(Wa1, ba1, Wb1, bb1, Wc1);
    k_reduceA<<<(MTOT + 255) / 256, 256>>>();
    k_segstat<<<BATCH, 256>>>(cids);
    k_w     <<<(MTOT + 255) / 256, 256>>>(cids);
    k_accum <<<dim3(16, BATCH), 512>>>(cids);
    k_reduceC<<<(NSEG * 512 + 255) / 256, 256>>>();
    k_intra <<<NSEG, 512>>>(Wi, bi, Wa2, ba2, Wb2, bb2, Wc2);
    k_final <<<BATCH, 512>>>(Wint, bint, Wcls, bcls, out);
}

// round 10
// speedup vs baseline: 1.7636x; 1.7636x over previous
#include <cuda_runtime.h>
#include <cuda_bf16.h>
#include <math.h>
#include <stdint.h>

// ---------------- problem constants ----------------
#define BATCH 8
#define NTOK  16384
#define MTOT  (BATCH * NTOK)      // 131072 tokens
#define NC    11                  // C+1 clusters
#define NSEG  (BATCH * NC)        // 88

// ---------------- scratch (device globals; no allocations allowed) ----------------
__device__ __nv_bfloat16 g_Xhi[(size_t)MTOT * 512];   // fused features, bf16 hi plane
__device__ __nv_bfloat16 g_Xlo[(size_t)MTOT * 512];   // bf16 lo (residual) plane
__device__ float g_Apart[2 * MTOT];
__device__ float g_A[MTOT];
__device__ float g_w[MTOT];
__device__ float g_pmax[64 * NC];
__device__ int   g_pcnt[64 * NC];
__device__ float g_psum[64 * NC];
__device__ float g_segmax[NSEG];
__device__ float g_segden[NSEG];
__device__ int   g_present[NSEG];
__device__ float g_cfeatPart[BATCH * 32 * NC * 512];
__device__ float g_cfeat[NSEG * 512];
__device__ float g_cf2[NSEG * 512];
__device__ float g_A2[NSEG];
// prepacked weights, K-major [N=512 rows][K=512], hi/lo bf16 split
__device__ __nv_bfloat16 g_Bf_hi[512 * 512];
__device__ __nv_bfloat16 g_Bf_lo[512 * 512];
__device__ __nv_bfloat16 g_Bab_hi[512 * 512];
__device__ __nv_bfloat16 g_Bab_lo[512 * 512];

__device__ __forceinline__ int clip_cid(int c) { return c < 0 ? 0 : (c > 10 ? 10 : c); }

__device__ __forceinline__ uint32_t smu(const void* p) {
    return (uint32_t)__cvta_generic_to_shared(p);
}

// ---------------- sm_90-baseline PTX helpers (valid at .target sm_103) ----------
#define CP_ASYNC16(dst, src) \
    asm volatile("cp.async.cg.shared.global [%0], [%1], 16;" :: "r"(dst), "l"(src))
#define CP_COMMIT() asm volatile("cp.async.commit_group;")
#define CP_WAIT0()  asm volatile("cp.async.wait_group 0;" ::: "memory")

__device__ __forceinline__ void ldsm4(uint32_t* r, uint32_t addr) {
    asm volatile("ldmatrix.sync.aligned.m8n8.x4.shared.b16 {%0,%1,%2,%3}, [%4];"
        : "=r"(r[0]), "=r"(r[1]), "=r"(r[2]), "=r"(r[3]) : "r"(addr));
}
__device__ __forceinline__ void mma4(float* d, const uint32_t* a, const uint32_t* b) {
    asm volatile(
        "mma.sync.aligned.m16n8k16.row.col.f32.bf16.bf16.f32 "
        "{%0,%1,%2,%3}, {%4,%5,%6,%7}, {%8,%9}, {%0,%1,%2,%3};"
        : "+f"(d[0]), "+f"(d[1]), "+f"(d[2]), "+f"(d[3])
        : "r"(a[0]), "r"(a[1]), "r"(a[2]), "r"(a[3]), "r"(b[0]), "r"(b[1]));
}

__device__ __forceinline__ void split2(float a, float b, uint32_t& hi, uint32_t& lo) {
    __nv_bfloat162 hp = __floats2bfloat162_rn(a, b);
    float ra = a - __low2float(hp);
    float rb = b - __high2float(hp);
    __nv_bfloat162 lp = __floats2bfloat162_rn(ra, rb);
    hi = *reinterpret_cast<uint32_t*>(&hp);
    lo = *reinterpret_cast<uint32_t*>(&lp);
}

// ---------------- GEMM tiling ----------------
// BM=128, BN=256, BK=16. 512 threads = 16 warps (4 m x 4 n), warp tile 32x64.
// SMEM rows padded to 48B (24 bf16) -> ldmatrix 8-row phases are bank-conflict-free.
#define RSB 48                         // row stride bytes (16 bf16 data + pad)
#define ST_AHI 0
#define ST_ALO 6144                    // 128*48
#define ST_BHI 12288
#define ST_BLO 24576                   // + 256*48
#define STAGE  36864
#define OFF_EPI  73728                 // 9216 B max epilogue constants
#define OFF_SRED 82944                 // 128*5*4 = 2560 B
#define SMEM_REQ 85504

// =====================================================================
// HMMA GEMM. EPI=0: fuse (h -> X hi/lo planes, bias+emb-tail+relu)
//            EPI=1: gate (X -> tanh*sigmoid dot Wc1 per-token partials)
// 3-term bf16 split: AhiBhi + AloBhi + AhiBlo.
// =====================================================================
template <int EPI>
__global__ __launch_bounds__(512) void k_gemm(
    const float* __restrict__ hsrc, const int* __restrict__ cids,
    const float* __restrict__ emb, const float* __restrict__ Wf,
    const float* __restrict__ bfu, const float* __restrict__ ba1,
    const float* __restrict__ bb1, const float* __restrict__ Wc1)
{
    extern __shared__ __align__(16) char dsm[];
    const int tid = threadIdx.x;
    const int lane = tid & 31, wid = tid >> 5;
    const int wm = wid >> 2, wn = wid & 3;
    const int colBase = blockIdx.x * 256;
    const int rowBase = blockIdx.y * 128;

    // ---- epilogue constants ----
    float* epi = (float*)(dsm + OFF_EPI);
    if (EPI == 0) {
        if (tid < 256) epi[tid] = bfu[colBase + tid];
        for (int i = tid; i < 2048; i += 512)
            epi[256 + i] = Wf[(512 + (i >> 8)) * 512 + colBase + (i & 255)];
    } else {
        if (tid < 128) {
            epi[tid]       = ba1[colBase / 2 + tid];
            epi[128 + tid] = bb1[colBase / 2 + tid];
            epi[256 + tid] = Wc1[colBase / 2 + tid];
        }
    }

    // ---- per-thread loader indices ----
    const __nv_bfloat16* Bh0 = (EPI == 0) ? g_Bf_hi : g_Bab_hi;
    const __nv_bfloat16* Bl0 = (EPI == 0) ? g_Bf_lo : g_Bab_lo;
    const uint32_t smBase = smu(dsm);

    const int rB = tid & 255, hB = tid >> 8;                 // B: 256 rows x 2 halves
    const char* srcBh = (const char*)(Bh0 + (size_t)(colBase + rB) * 512) + hB * 16;
    const char* srcBl = (const char*)(Bl0 + (size_t)(colBase + rB) * 512) + hB * 16;
    const uint32_t dstBoff = rB * RSB + hB * 16;

    // GEMM1 A loader (fp32 h, runtime split)
    const int rA = tid >> 2, cq = tid & 3;
    const float* srcA1 = (EPI == 0) ? (hsrc + (size_t)(rowBase + rA) * 512 + cq * 4) : nullptr;
    const uint32_t dstA1off = rA * RSB + cq * 8;
    // GEMM2 A loader (pre-split planes, byte copy)
    const int plA = tid >> 8, idxA = tid & 255, rA2 = idxA >> 1, hA = idxA & 1;
    const char* srcA2 = (const char*)(((plA ? g_Xlo : g_Xhi)
                          + (size_t)(rowBase + rA2) * 512)) + hA * 16;
    const uint32_t dstA2off = (plA ? ST_ALO : ST_AHI) + rA2 * RSB + hA * 16;

    // ---- ldmatrix addresses (per thread, per plane-relative) ----
    uint32_t offA[2], offB[4];
    {
        int rowAf = wm * 32 + (lane & 15);
        int kAf = (lane >> 4) * 8;
#pragma unroll
        for (int mt = 0; mt < 2; mt++) offA[mt] = (rowAf + mt * 16) * RSB + kAf * 2;
        int rowBf = wn * 64 + (lane & 7) + 8 * (lane >> 4);
        int kBf = ((lane >> 3) & 1) * 8;
#pragma unroll
        for (int nf2 = 0; nf2 < 4; nf2++) offB[nf2] = (rowBf + nf2 * 16) * RSB + kBf * 2;
    }

    // ---- preamble: stage 0 ----
    {
        uint32_t db = smBase;
        CP_ASYNC16(db + ST_BHI + dstBoff, srcBh);
        CP_ASYNC16(db + ST_BLO + dstBoff, srcBl);
        if (EPI != 0) CP_ASYNC16(db + dstA2off, srcA2);
        CP_COMMIT();
        if (EPI == 0) {
            float4 v = *(const float4*)srcA1;
            uint32_t h0, l0, h1, l1;
            split2(v.x, v.y, h0, l0);
            split2(v.z, v.w, h1, l1);
            *(uint2*)(dsm + ST_AHI + dstA1off) = make_uint2(h0, h1);
            *(uint2*)(dsm + ST_ALO + dstA1off) = make_uint2(l0, l1);
        }
        CP_WAIT0();
    }
    __syncthreads();

    float acc[2][8][4];
#pragma unroll
    for (int i = 0; i < 2; i++)
#pragma unroll
        for (int j = 0; j < 8; j++)
#pragma unroll
            for (int k = 0; k < 4; k++) acc[i][j][k] = 0.0f;

    // ---- main loop: 32 k-iters of BK=16, double buffered ----
#pragma unroll 1
    for (int ks = 0; ks < 32; ks++) {
        const int buf = ks & 1;
        float4 av;
        if (ks < 31) {
            uint32_t db = smBase + (buf ^ 1) * STAGE;
            CP_ASYNC16(db + ST_BHI + dstBoff, srcBh + (ks + 1) * 32);
            CP_ASYNC16(db + ST_BLO + dstBoff, srcBl + (ks + 1) * 32);
            if (EPI != 0) CP_ASYNC16(db + dstA2off, srcA2 + (ks + 1) * 32);
            CP_COMMIT();
            if (EPI == 0) av = *(const float4*)(srcA1 + (ks + 1) * 16);
        }

        // compute on buf
        const uint32_t sb = smBase + buf * STAGE;
        uint32_t ah[2][4], al[2][4];
        ldsm4(ah[0], sb + ST_AHI + offA[0]);
        ldsm4(ah[1], sb + ST_AHI + offA[1]);
        ldsm4(al[0], sb + ST_ALO + offA[0]);
        ldsm4(al[1], sb + ST_ALO + offA[1]);
#pragma unroll
        for (int nf2 = 0; nf2 < 4; nf2++) {
            uint32_t bh[4], bl[4];
            ldsm4(bh, sb + ST_BHI + offB[nf2]);
            mma4(acc[0][2 * nf2], ah[0], bh);  mma4(acc[0][2 * nf2 + 1], ah[0], bh + 2);
            mma4(acc[1][2 * nf2], ah[1], bh);  mma4(acc[1][2 * nf2 + 1], ah[1], bh + 2);
            mma4(acc[0][2 * nf2], al[0], bh);  mma4(acc[0][2 * nf2 + 1], al[0], bh + 2);
            mma4(acc[1][2 * nf2], al[1], bh);  mma4(acc[1][2 * nf2 + 1], al[1], bh + 2);
            ldsm4(bl, sb + ST_BLO + offB[nf2]);
            mma4(acc[0][2 * nf2], ah[0], bl);  mma4(acc[0][2 * nf2 + 1], ah[0], bl + 2);
            mma4(acc[1][2 * nf2], ah[1], bl);  mma4(acc[1][2 * nf2 + 1], ah[1], bl + 2);
        }

        if (ks < 31) {
            if (EPI == 0) {
                uint32_t h0, l0, h1, l1;
                split2(av.x, av.y, h0, l0);
                split2(av.z, av.w, h1, l1);
                char* db = dsm + (buf ^ 1) * STAGE;
                *(uint2*)(db + ST_AHI + dstA1off) = make_uint2(h0, h1);
                *(uint2*)(db + ST_ALO + dstA1off) = make_uint2(l0, l1);
            }
            CP_WAIT0();
            __syncthreads();
        }
    }

    // ---- epilogue ----
    const int q = lane >> 2, p = lane & 3;
    if (EPI == 0) {
#pragma unroll
        for (int mt = 0; mt < 2; mt++)
#pragma unroll
            for (int half = 0; half < 2; half++) {
                int r = rowBase + wm * 32 + mt * 16 + q + 8 * half;
                int cid = clip_cid(cids[r]);
                float ev[8];
#pragma unroll
                for (int e = 0; e < 8; e++) ev[e] = emb[cid * 8 + e];
#pragma unroll
                for (int nf = 0; nf < 8; nf++) {
                    int cl = wn * 64 + nf * 8 + 2 * p;
                    float v0 = acc[mt][nf][2 * half]     + epi[cl];
                    float v1 = acc[mt][nf][2 * half + 1] + epi[cl + 1];
#pragma unroll
                    for (int e = 0; e < 8; e++) {
                        v0 = fmaf(ev[e], epi[256 + e * 256 + cl], v0);
                        v1 = fmaf(ev[e], epi[256 + e * 256 + cl + 1], v1);
                    }
                    v0 = fmaxf(v0, 0.0f);
                    v1 = fmaxf(v1, 0.0f);
                    uint32_t hi, lo;
                    split2(v0, v1, hi, lo);
                    size_t go = (size_t)r * 512 + colBase + cl;
                    *reinterpret_cast<uint32_t*>(g_Xhi + go) = hi;
                    *reinterpret_cast<uint32_t*>(g_Xlo + go) = lo;
                }
            }
    } else {
        float* sred = (float*)(dsm + OFF_SRED);
#pragma unroll
        for (int mt = 0; mt < 2; mt++)
#pragma unroll
            for (int half = 0; half < 2; half++) {
                float s = 0.0f;
#pragma unroll
                for (int nf = 0; nf < 8; nf++) {
                    int jl = wn * 32 + nf * 4 + p;
                    float va = acc[mt][nf][2 * half]     + epi[jl];
                    float vg = acc[mt][nf][2 * half + 1] + epi[128 + jl];
                    float a = tanhf(va);
                    float gg = 1.0f / (1.0f + expf(-vg));
                    s = fmaf(a * gg, epi[256 + jl], s);
                }
                s += __shfl_xor_sync(0xFFFFFFFFu, s, 1);
                s += __shfl_xor_sync(0xFFFFFFFFu, s, 2);
                if (p == 0)
                    sred[(wm * 32 + mt * 16 + q + 8 * half) * 5 + wn] = s;
            }
        __syncthreads();
        if (tid < 128) {
            float t = sred[tid * 5] + sred[tid * 5 + 1] + sred[tid * 5 + 2] + sred[tid * 5 + 3];
            g_Apart[(size_t)blockIdx.x * MTOT + rowBase + tid] = t;
        }
    }
}

// =====================================================================
// Weight prepack: fp32 [K,N] -> bf16 hi/lo K-major [N,K]
// =====================================================================
__global__ __launch_bounds__(256) void k_pack_wf(const float* __restrict__ Wf) {
    int n = blockIdx.x;
    for (int k = threadIdx.x; k < 512; k += 256) {
        float x = Wf[k * 512 + n];
        __nv_bfloat16 hi = __float2bfloat16(x);
        __nv_bfloat16 lo = __float2bfloat16(x - __bfloat162float(hi));
        g_Bf_hi[n * 512 + k] = hi;
        g_Bf_lo[n * 512 + k] = lo;
    }
}
// interleave: row 2p = Wa1 col p, row 2p+1 = Wb1 col p
__global__ __launch_bounds__(256) void k_pack_wab(const float* __restrict__ Wa1,
                                                  const float* __restrict__ Wb1) {
    int n = blockIdx.x;
    int p = n >> 1;
    const float* src = (n & 1) ? Wb1 : Wa1;
    for (int k = threadIdx.x; k < 512; k += 256) {
        float x = src[k * 256 + p];
        __nv_bfloat16 hi = __float2bfloat16(x);
        __nv_bfloat16 lo = __float2bfloat16(x - __bfloat162float(hi));
        g_Bab_hi[n * 512 + k] = hi;
        g_Bab_lo[n * 512 + k] = lo;
    }
}

__global__ void k_reduceA() {
    int t = blockIdx.x * blockDim.x + threadIdx.x;
    if (t >= MTOT) return;
    g_A[t] = g_Apart[t] + g_Apart[(size_t)MTOT + t];
}

// =====================================================================
// Segment stats: 64-way partials (8 chunks x 8 batches), then tiny combines
// =====================================================================
__global__ __launch_bounds__(256) void k_segpart(const int* __restrict__ cids) {
    __shared__ float sm[NC * 256];
    __shared__ int   sc[NC * 256];
    const int blk = blockIdx.x, b = blk >> 3, ch = blk & 7, tid = threadIdx.x;
    for (int c = 0; c < NC; c++) { sm[c * 256 + tid] = -3.0e38f; sc[c * 256 + tid] = 0; }
    const int base = b * NTOK + ch * 2048;
    for (int it = 0; it < 8; it++) {
        int t = base + it * 256 + tid;
        int c = clip_cid(cids[t]);
        float v = g_A[t];
        if (v > sm[c * 256 + tid]) sm[c * 256 + tid] = v;
        sc[c * 256 + tid]++;
    }
    __syncthreads();
    if (tid < NC) {
        float m = -3.0e38f; int cnt = 0;
        for (int i = 0; i < 256; i++) { m = fmaxf(m, sm[tid * 256 + i]); cnt += sc[tid * 256 + i]; }
        g_pmax[blk * NC + tid] = m;
        g_pcnt[blk * NC + tid] = cnt;
    }
}
__global__ void k_segfin() {
    int s = threadIdx.x;
    if (s >= NSEG) return;
    int b = s / NC, c = s % NC;
    float m = -3.0e38f; int cnt = 0;
    for (int ch = 0; ch < 8; ch++) {
        m = fmaxf(m, g_pmax[(b * 8 + ch) * NC + c]);
        cnt += g_pcnt[(b * 8 + ch) * NC + c];
    }
    g_segmax[s] = (cnt > 0) ? m : 0.0f;
    g_present[s] = (cnt > 0) ? 1 : 0;
}
__global__ __launch_bounds__(256) void k_segexp(const int* __restrict__ cids) {
    __shared__ float sm[NC * 256];
    __shared__ float fm[NC];
    const int blk = blockIdx.x, b = blk >> 3, ch = blk & 7, tid = threadIdx.x;
    if (tid < NC) fm[tid] = g_segmax[b * NC + tid];
    for (int c = 0; c < NC; c++) sm[c * 256 + tid] = 0.0f;
    __syncthreads();
    const int base = b * NTOK + ch * 2048;
    for (int it = 0; it < 8; it++) {
        int t = base + it * 256 + tid;
        int c = clip_cid(cids[t]);
        sm[c * 256 + tid] += expf(g_A[t] - fm[c]);
    }
    __syncthreads();
    if (tid < NC) {
        float s = 0.0f;
        for (int i = 0; i < 256; i++) s += sm[tid * 256 + i];
        g_psum[blk * NC + tid] = s;
    }
}
__global__ void k_segfin2() {
    int s = threadIdx.x;
    if (s >= NSEG) return;
    int b = s / NC, c = s % NC;
    float d = 0.0f;
    for (int ch = 0; ch < 8; ch++) d += g_psum[(b * 8 + ch) * NC + c];
    g_segden[s] = d;
}
__global__ void k_w(const int* __restrict__ cids) {
    int t = blockIdx.x * blockDim.x + threadIdx.x;
    if (t >= MTOT) return;
    int b = t >> 14;
    int c = clip_cid(cids[t]);
    g_w[t] = expf(g_A[t] - g_segmax[b * NC + c]) / g_segden[b * NC + c];
}

// =====================================================================
// Segment-sum of w-weighted X (hi+lo reconstruct), deterministic partials
// =====================================================================
__global__ __launch_bounds__(512) void k_accum(const int* __restrict__ cids) {
    __shared__ float acc[NC * 512];
    const int chunk = blockIdx.x, b = blockIdx.y, tid = threadIdx.x;
    for (int i = tid; i < NC * 512; i += 512) acc[i] = 0.0f;
    __syncthreads();
    const int base = b * NTOK + chunk * 512;
    for (int it = 0; it < 512; it++) {
        int row = base + it;
        int c = clip_cid(cids[row]);
        float wv = g_w[row];
        size_t off = (size_t)row * 512 + tid;
        float x = __bfloat162float(g_Xhi[off]) + __bfloat162float(g_Xlo[off]);
        acc[c * 512 + tid] += x * wv;
    }
    __syncthreads();
    float* dst = &g_cfeatPart[(size_t)(b * 32 + chunk) * NC * 512];
    for (int c = 0; c < NC; c++) dst[c * 512 + tid] = acc[c * 512 + tid];
}
__global__ void k_reduceC() {
    int idx = blockIdx.x * blockDim.x + threadIdx.x;
    if (idx >= NSEG * 512) return;
    int b = idx / (NC * 512);
    int off = idx % (NC * 512);
    float s = 0.0f;
#pragma unroll
    for (int j = 0; j < 32; j++) s += g_cfeatPart[(size_t)(b * 32 + j) * NC * 512 + off];
    g_cfeat[idx] = s;
}

// =====================================================================
// Per-cluster-row MLP + gated attention-2 logit (88 rows)
// =====================================================================
__global__ __launch_bounds__(512) void k_intra(
    const float* __restrict__ Wi, const float* __restrict__ bi,
    const float* __restrict__ Wa2, const float* __restrict__ ba2,
    const float* __restrict__ Wb2, const float* __restrict__ bb2,
    const float* __restrict__ Wc2)
{
    __shared__ float cfr[512];
    __shared__ float cf2s[512];
    __shared__ float red[256];
    const int row = blockIdx.x, tid = threadIdx.x;

    cfr[tid] = g_cfeat[row * 512 + tid];
    __syncthreads();
    float s = bi[tid];
    for (int k = 0; k < 512; k++) s = fmaf(cfr[k], Wi[k * 512 + tid], s);
    s = fmaxf(s, 0.0f);
    cf2s[tid] = s;
    g_cf2[row * 512 + tid] = s;
    __syncthreads();
    if (tid < 256) {
        float sa = ba2[tid], sg = bb2[tid];
        for (int k = 0; k < 512; k++) {
            float v = cf2s[k];
            sa = fmaf(v, Wa2[k * 256 + tid], sa);
            sg = fmaf(v, Wb2[k * 256 + tid], sg);
        }
        float a = tanhf(sa);
        float gg = 1.0f / (1.0f + expf(-sg));
        red[tid] = a * gg * Wc2[tid];
    }
    __syncthreads();
    for (int sft = 128; sft > 0; sft >>= 1) {
        if (tid < sft && tid + sft < 256) red[tid] += red[tid + sft];
        __syncthreads();
    }
    if (tid == 0) g_A2[row] = red[0];
}

// =====================================================================
// Per-batch masked softmax over clusters, slide pooling, head MLP
// =====================================================================
__global__ __launch_bounds__(512) void k_final(
    const float* __restrict__ Wint, const float* __restrict__ bint,
    const float* __restrict__ Wcls, const float* __restrict__ bcls,
    float* __restrict__ out)
{
    __shared__ float Wsm[NC];
    __shared__ float slide[512];
    __shared__ float inter[256];
    const int b = blockIdx.x, tid = threadIdx.x;

    if (tid == 0) {
        float av[NC];
        float m = -3.0e38f;
        for (int c = 0; c < NC; c++) {
            av[c] = g_present[b * NC + c] ? g_A2[b * NC + c] : -3.0e38f;
            m = fmaxf(m, av[c]);
        }
        float sden = 0.0f;
        float ex[NC];
        for (int c = 0; c < NC; c++) { ex[c] = expf(av[c] - m); sden += ex[c]; }
        for (int c = 0; c < NC; c++) Wsm[c] = ex[c] / sden;
    }
    __syncthreads();
    float sv = 0.0f;
    for (int c = 0; c < NC; c++) sv = fmaf(Wsm[c], g_cf2[(b * NC + c) * 512 + tid], sv);
    slide[tid] = sv;
    __syncthreads();
    if (tid < 256) {
        float v = bint[tid];
        for (int k = 0; k < 512; k++) v = fmaf(slide[k], Wint[k * 256 + tid], v);
        inter[tid] = fmaxf(v, 0.0f);
    }
    __syncthreads();
    if (tid < 2) {
        float o = bcls[tid];
        for (int k = 0; k < 256; k++) o = fmaf(inter[k], Wcls[k * 2 + tid], o);
        out[b * 2 + tid] = o;
    }
}

// =====================================================================
extern "C" void kernel_launch(void* const* d_in, const int* in_sizes, int n_in,
                              void* d_out, int out_size)
{
    const float* h    = (const float*)d_in[0];
    const int*   cids = (const int*)  d_in[1];
    const float* emb  = (const float*)d_in[2];
    const float* Wf   = (const float*)d_in[3];
    const float* bfu  = (const float*)d_in[4];
    const float* Wa1  = (const float*)d_in[5];
    const float* ba1  = (const float*)d_in[6];
    const float* Wb1  = (const float*)d_in[7];
    const float* bb1  = (const float*)d_in[8];
    const float* Wc1  = (const float*)d_in[9];
    // d_in[10] = bc1: constant shift inside segment softmax -> cancels exactly
    const float* Wi   = (const float*)d_in[11];
    const float* bi   = (const float*)d_in[12];
    const float* Wa2  = (const float*)d_in[13];
    const float* ba2  = (const float*)d_in[14];
    const float* Wb2  = (const float*)d_in[15];
    const float* bb2  = (const float*)d_in[16];
    const float* Wc2  = (const float*)d_in[17];
    // d_in[18] = bc2: cancels in inter-cluster softmax
    const float* Wint = (const float*)d_in[19];
    const float* bint = (const float*)d_in[20];
    const float* Wcls = (const float*)d_in[21];
    const float* bcls = (const float*)d_in[22];
    float* out = (float*)d_out;

    cudaFuncSetAttribute(k_gemm<0>, cudaFuncAttributeMaxDynamicSharedMemorySize, SMEM_REQ);
    cudaFuncSetAttribute(k_gemm<1>, cudaFuncAttributeMaxDynamicSharedMemorySize, SMEM_REQ);

    k_pack_wf <<<512, 256>>>(Wf);
    k_pack_wab<<<512, 256>>>(Wa1, Wb1);
    k_gemm<0> <<<dim3(2, 1024), 512, SMEM_REQ>>>(h, cids, emb, Wf, bfu, nullptr, nullptr, nullptr);
    k_gemm<1> <<<dim3(2, 1024), 512, SMEM_REQ>>>(nullptr, cids, emb, Wf, bfu, ba1, bb1, Wc1);
    k_reduceA <<<(MTOT + 255) / 256, 256>>>();
    k_segpart <<<64, 256>>>(cids);
    k_segfin  <<<1, 128>>>();
    k_segexp  <<<64, 256>>>(cids);
    k_segfin2 <<<1, 128>>>();
    k_w       <<<(MTOT + 255) / 256, 256>>>(cids);
    k_accum   <<<dim3(32, BATCH), 512>>>(cids);
    k_reduceC <<<(NSEG * 512 + 255) / 256, 256>>>();
    k_intra   <<<NSEG, 512>>>(Wi, bi, Wa2, ba2, Wb2, bb2, Wc2);
    k_final   <<<BATCH, 512>>>(Wint, bint, Wcls, bcls, out);
}

// round 12
// speedup vs baseline: 1.8211x; 1.0326x over previous
#include <cuda_runtime.h>
#include <cuda_bf16.h>
#include <math.h>
#include <stdint.h>

// ---------------- problem constants ----------------
#define BATCH 8
#define NTOK  16384
#define MTOT  (BATCH * NTOK)      // 131072 tokens
#define NC    11                  // C+1 clusters
#define NSEG  (BATCH * NC)        // 88

// ---------------- scratch (device globals; no allocations allowed) ----------------
__device__ __nv_bfloat16 g_Xhi[(size_t)MTOT * 512];   // fused features, bf16 hi plane
__device__ __nv_bfloat16 g_Xlo[(size_t)MTOT * 512];   // bf16 lo (residual) plane
__device__ float g_Apart[2 * MTOT];
__device__ float g_A[MTOT];
__device__ float g_w[MTOT];
__device__ float g_pmax[64 * NC];
__device__ int   g_pcnt[64 * NC];
__device__ float g_psum[64 * NC];
__device__ float g_segmax[NSEG];
__device__ float g_segden[NSEG];
__device__ int   g_present[NSEG];
__device__ float g_cfeatPart[BATCH * 64 * NC * 512];
__device__ float g_cfeat[NSEG * 512];
__device__ float g_cf2[NSEG * 512];
__device__ float g_A2[NSEG];
// prepacked weights, K-major [N=512 rows][K=512], hi/lo bf16 split
__device__ __nv_bfloat16 g_Bf_hi[512 * 512];
__device__ __nv_bfloat16 g_Bf_lo[512 * 512];
__device__ __nv_bfloat16 g_Bab_hi[512 * 512];
__device__ __nv_bfloat16 g_Bab_lo[512 * 512];

__device__ __forceinline__ int clip_cid(int c) { return c < 0 ? 0 : (c > 10 ? 10 : c); }

__device__ __forceinline__ uint32_t smu(const void* p) {
    return (uint32_t)__cvta_generic_to_shared(p);
}

// ---------------- sm_90-baseline PTX helpers (valid at .target sm_103) ----------
#define CP_ASYNC16(dst, src) \
    asm volatile("cp.async.cg.shared.global [%0], [%1], 16;" :: "r"(dst), "l"(src))
#define CP_COMMIT() asm volatile("cp.async.commit_group;")
#define CP_WAIT0()  asm volatile("cp.async.wait_group 0;" ::: "memory")
#define CP_WAIT1()  asm volatile("cp.async.wait_group 1;" ::: "memory")

__device__ __forceinline__ void ldsm4(uint32_t* r, uint32_t addr) {
    asm volatile("ldmatrix.sync.aligned.m8n8.x4.shared.b16 {%0,%1,%2,%3}, [%4];"
        : "=r"(r[0]), "=r"(r[1]), "=r"(r[2]), "=r"(r[3]) : "r"(addr));
}
__device__ __forceinline__ void mma4(float* d, const uint32_t* a, const uint32_t* b) {
    asm volatile(
        "mma.sync.aligned.m16n8k16.row.col.f32.bf16.bf16.f32 "
        "{%0,%1,%2,%3}, {%4,%5,%6,%7}, {%8,%9}, {%0,%1,%2,%3};"
        : "+f"(d[0]), "+f"(d[1]), "+f"(d[2]), "+f"(d[3])
        : "r"(a[0]), "r"(a[1]), "r"(a[2]), "r"(a[3]), "r"(b[0]), "r"(b[1]));
}

__device__ __forceinline__ void split2(float a, float b, uint32_t& hi, uint32_t& lo) {
    __nv_bfloat162 hp = __floats2bfloat162_rn(a, b);
    float ra = a - __low2float(hp);
    float rb = b - __high2float(hp);
    __nv_bfloat162 lp = __floats2bfloat162_rn(ra, rb);
    hi = *reinterpret_cast<uint32_t*>(&hp);
    lo = *reinterpret_cast<uint32_t*>(&lp);
}

// ---------------- GEMM tiling ----------------
// BM=128, BN=256, BK=16. 512 threads = 16 warps (4 m x 4 n), warp tile 32x64.
// SMEM rows padded to 48B -> ldmatrix 8-row phases conflict-free.
// 3-stage cp.async ring, wait_group 1: loads get ~2 compute phases of slack.
#define RSB 48                         // row stride bytes (16 bf16 data + pad)
#define ST_AHI 0
#define ST_ALO 6144                    // 128*48
#define ST_BHI 12288
#define ST_BLO 24576                   // + 256*48
#define STAGE  36864
#define NSTAGES 3
#define OFF_EPI  110592                // 3*STAGE
#define OFF_SRED 119808                // +9216
#define SMEM_REQ 122368                // +2560

// =====================================================================
// HMMA GEMM. EPI=0: fuse (h -> X hi/lo planes, bias+emb-tail+relu)
//            EPI=1: gate (X -> tanh*sigmoid dot Wc1 per-token partials)
// 3-term bf16 split: AhiBhi + AloBhi + AhiBlo.
// =====================================================================
template <int EPI>
__global__ __launch_bounds__(512) void k_gemm(
    const float* __restrict__ hsrc, const int* __restrict__ cids,
    const float* __restrict__ emb, const float* __restrict__ Wf,
    const float* __restrict__ bfu, const float* __restrict__ ba1,
    const float* __restrict__ bb1, const float* __restrict__ Wc1)
{
    extern __shared__ __align__(16) char dsm[];
    const int tid = threadIdx.x;
    const int lane = tid & 31, wid = tid >> 5;
    const int wm = wid >> 2, wn = wid & 3;
    const int colBase = blockIdx.x * 256;
    const int rowBase = blockIdx.y * 128;

    // ---- epilogue constants ----
    float* epi = (float*)(dsm + OFF_EPI);
    if (EPI == 0) {
        if (tid < 256) epi[tid] = bfu[colBase + tid];
        for (int i = tid; i < 2048; i += 512)
            epi[256 + i] = Wf[(512 + (i >> 8)) * 512 + colBase + (i & 255)];
    } else {
        if (tid < 128) {
            epi[tid]       = ba1[colBase / 2 + tid];
            epi[128 + tid] = bb1[colBase / 2 + tid];
            epi[256 + tid] = Wc1[colBase / 2 + tid];
        }
    }

    // ---- per-thread loader indices ----
    const __nv_bfloat16* Bh0 = (EPI == 0) ? g_Bf_hi : g_Bab_hi;
    const __nv_bfloat16* Bl0 = (EPI == 0) ? g_Bf_lo : g_Bab_lo;
    const uint32_t smBase = smu(dsm);

    const int rB = tid & 255, hB = tid >> 8;                 // B: 256 rows x 2 halves
    const char* srcBh = (const char*)(Bh0 + (size_t)(colBase + rB) * 512) + hB * 16;
    const char* srcBl = (const char*)(Bl0 + (size_t)(colBase + rB) * 512) + hB * 16;
    const uint32_t dstBoff = rB * RSB + hB * 16;

    // GEMM1 A loader (fp32 h, runtime split)
    const int rA = tid >> 2, cq = tid & 3;
    const float* srcA1 = (EPI == 0) ? (hsrc + (size_t)(rowBase + rA) * 512 + cq * 4) : nullptr;
    const uint32_t dstA1off = rA * RSB + cq * 8;
    // GEMM2 A loader (pre-split planes, byte copy)
    const int plA = tid >> 8, idxA = tid & 255, rA2 = idxA >> 1, hA = idxA & 1;
    const char* srcA2 = (const char*)(((plA ? g_Xlo : g_Xhi)
                          + (size_t)(rowBase + rA2) * 512)) + hA * 16;
    const uint32_t dstA2off = (plA ? ST_ALO : ST_AHI) + rA2 * RSB + hA * 16;

    // ---- ldmatrix addresses (per thread, per plane-relative) ----
    uint32_t offA[2], offB[4];
    {
        int rowAf = wm * 32 + (lane & 15);
        int kAf = (lane >> 4) * 8;
#pragma unroll
        for (int mt = 0; mt < 2; mt++) offA[mt] = (rowAf + mt * 16) * RSB + kAf * 2;
        int rowBf = wn * 64 + (lane & 7) + 8 * (lane >> 4);
        int kBf = ((lane >> 3) & 1) * 8;
#pragma unroll
        for (int nf2 = 0; nf2 < 4; nf2++) offB[nf2] = (rowBf + nf2 * 16) * RSB + kBf * 2;
    }

    // ---- preamble: stages 0 and 1 ----
#pragma unroll
    for (int s = 0; s < 2; s++) {
        uint32_t db = smBase + s * STAGE;
        CP_ASYNC16(db + ST_BHI + dstBoff, srcBh + s * 32);
        CP_ASYNC16(db + ST_BLO + dstBoff, srcBl + s * 32);
        if (EPI != 0) CP_ASYNC16(db + dstA2off, srcA2 + s * 32);
        CP_COMMIT();
        if (EPI == 0) {
            float4 v = *(const float4*)(srcA1 + s * 16);
            uint32_t h0, l0, h1, l1;
            split2(v.x, v.y, h0, l0);
            split2(v.z, v.w, h1, l1);
            char* dc = dsm + s * STAGE;
            *(uint2*)(dc + ST_AHI + dstA1off) = make_uint2(h0, h1);
            *(uint2*)(dc + ST_ALO + dstA1off) = make_uint2(l0, l1);
        }
    }
    CP_WAIT1();          // stage 0 landed (stage 1 may be in flight)
    __syncthreads();

    float acc[2][8][4];
#pragma unroll
    for (int i = 0; i < 2; i++)
#pragma unroll
        for (int j = 0; j < 8; j++)
#pragma unroll
            for (int k = 0; k < 4; k++) acc[i][j][k] = 0.0f;

    // ---- main loop: 32 k-iters of BK=16, 3-stage ring ----
    int buf = 0;
#pragma unroll 1
    for (int ks = 0; ks < 32; ks++) {
        int nbuf = buf + 2; if (nbuf >= NSTAGES) nbuf -= NSTAGES;
        float4 av;
        if (ks < 30) {
            // prefetch stage ks+2 into nbuf (== buffer computed at iter ks-1;
            // the trailing sync of iter ks-1 separates the overwrite)
            uint32_t db = smBase + nbuf * STAGE;
            CP_ASYNC16(db + ST_BHI + dstBoff, srcBh + (ks + 2) * 32);
            CP_ASYNC16(db + ST_BLO + dstBoff, srcBl + (ks + 2) * 32);
            if (EPI != 0) CP_ASYNC16(db + dstA2off, srcA2 + (ks + 2) * 32);
            CP_COMMIT();
            if (EPI == 0) av = *(const float4*)(srcA1 + (ks + 2) * 16);
        }

        // compute on buf (stage ks)
        const uint32_t sb = smBase + buf * STAGE;
        uint32_t ah[2][4], al[2][4];
        ldsm4(ah[0], sb + ST_AHI + offA[0]);
        ldsm4(ah[1], sb + ST_AHI + offA[1]);
        ldsm4(al[0], sb + ST_ALO + offA[0]);
        ldsm4(al[1], sb + ST_ALO + offA[1]);
#pragma unroll
        for (int nf2 = 0; nf2 < 4; nf2++) {
            uint32_t bh[4], bl[4];
            ldsm4(bh, sb + ST_BHI + offB[nf2]);
            mma4(acc[0][2 * nf2], ah[0], bh);  mma4(acc[0][2 * nf2 + 1], ah[0], bh + 2);
            mma4(acc[1][2 * nf2], ah[1], bh);  mma4(acc[1][2 * nf2 + 1], ah[1], bh + 2);
            mma4(acc[0][2 * nf2], al[0], bh);  mma4(acc[0][2 * nf2 + 1], al[0], bh + 2);
            mma4(acc[1][2 * nf2], al[1], bh);  mma4(acc[1][2 * nf2 + 1], al[1], bh + 2);
            ldsm4(bl, sb + ST_BLO + offB[nf2]);
            mma4(acc[0][2 * nf2], ah[0], bl);  mma4(acc[0][2 * nf2 + 1], ah[0], bl + 2);
            mma4(acc[1][2 * nf2], ah[1], bl);  mma4(acc[1][2 * nf2 + 1], ah[1], bl + 2);
        }

        if (ks < 30 && EPI == 0) {
            uint32_t h0, l0, h1, l1;
            split2(av.x, av.y, h0, l0);
            split2(av.z, av.w, h1, l1);
            char* dc = dsm + nbuf * STAGE;
            *(uint2*)(dc + ST_AHI + dstA1off) = make_uint2(h0, h1);
            *(uint2*)(dc + ST_ALO + dstA1off) = make_uint2(l0, l1);
        }
        if (ks < 31) {
            if (ks < 30) { CP_WAIT1(); }   // stage ks+1 complete; ks+2 in flight
            else         { CP_WAIT0(); }   // last stage (31) complete
            __syncthreads();
        }
        buf = buf + 1; if (buf >= NSTAGES) buf -= NSTAGES;
    }

    // ---- epilogue ----
    const int q = lane >> 2, p = lane & 3;
    if (EPI == 0) {
#pragma unroll
        for (int mt = 0; mt < 2; mt++)
#pragma unroll
            for (int half = 0; half < 2; half++) {
                int r = rowBase + wm * 32 + mt * 16 + q + 8 * half;
                int cid = clip_cid(cids[r]);
                float ev[8];
#pragma unroll
                for (int e = 0; e < 8; e++) ev[e] = emb[cid * 8 + e];
#pragma unroll
                for (int nf = 0; nf < 8; nf++) {
                    int cl = wn * 64 + nf * 8 + 2 * p;
                    float v0 = acc[mt][nf][2 * half]     + epi[cl];
                    float v1 = acc[mt][nf][2 * half + 1] + epi[cl + 1];
#pragma unroll
                    for (int e = 0; e < 8; e++) {
                        v0 = fmaf(ev[e], epi[256 + e * 256 + cl], v0);
                        v1 = fmaf(ev[e], epi[256 + e * 256 + cl + 1], v1);
                    }
                    v0 = fmaxf(v0, 0.0f);
                    v1 = fmaxf(v1, 0.0f);
                    uint32_t hi, lo;
                    split2(v0, v1, hi, lo);
                    size_t go = (size_t)r * 512 + colBase + cl;
                    *reinterpret_cast<uint32_t*>(g_Xhi + go) = hi;
                    *reinterpret_cast<uint32_t*>(g_Xlo + go) = lo;
                }
            }
    } else {
        float* sred = (float*)(dsm + OFF_SRED);
#pragma unroll
        for (int mt = 0; mt < 2; mt++)
#pragma unroll
            for (int half = 0; half < 2; half++) {
                float s = 0.0f;
#pragma unroll
                for (int nf = 0; nf < 8; nf++) {
                    int jl = wn * 32 + nf * 4 + p;
                    float va = acc[mt][nf][2 * half]     + epi[jl];
                    float vg = acc[mt][nf][2 * half + 1] + epi[128 + jl];
                    float a = tanhf(va);
                    float gg = 1.0f / (1.0f + expf(-vg));
                    s = fmaf(a * gg, epi[256 + jl], s);
                }
                s += __shfl_xor_sync(0xFFFFFFFFu, s, 1);
                s += __shfl_xor_sync(0xFFFFFFFFu, s, 2);
                if (p == 0)
                    sred[(wm * 32 + mt * 16 + q + 8 * half) * 5 + wn] = s;
            }
        __syncthreads();
        if (tid < 128) {
            float t = sred[tid * 5] + sred[tid * 5 + 1] + sred[tid * 5 + 2] + sred[tid * 5 + 3];
            g_Apart[(size_t)blockIdx.x * MTOT + rowBase + tid] = t;
        }
    }
}

// =====================================================================
// Weight prepack: fp32 [K,N] -> bf16 hi/lo K-major [N,K]
// =====================================================================
__global__ __launch_bounds__(256) void k_pack_wf(const float* __restrict__ Wf) {
    int n = blockIdx.x;
    for (int k = threadIdx.x; k < 512; k += 256) {
        float x = Wf[k * 512 + n];
        __nv_bfloat16 hi = __float2bfloat16(x);
        __nv_bfloat16 lo = __float2bfloat16(x - __bfloat162float(hi));
        g_Bf_hi[n * 512 + k] = hi;
        g_Bf_lo[n * 512 + k] = lo;
    }
}
// interleave: row 2p = Wa1 col p, row 2p+1 = Wb1 col p
__global__ __launch_bounds__(256) void k_pack_wab(const float* __restrict__ Wa1,
                                                  const float* __restrict__ Wb1) {
    int n = blockIdx.x;
    int p = n >> 1;
    const float* src = (n & 1) ? Wb1 : Wa1;
    for (int k = threadIdx.x; k < 512; k += 256) {
        float x = src[k * 256 + p];
        __nv_bfloat16 hi = __float2bfloat16(x);
        __nv_bfloat16 lo = __float2bfloat16(x - __bfloat162float(hi));
        g_Bab_hi[n * 512 + k] = hi;
        g_Bab_lo[n * 512 + k] = lo;
    }
}

__global__ void k_reduceA() {
    int t = blockIdx.x * blockDim.x + threadIdx.x;
    if (t >= MTOT) return;
    g_A[t] = g_Apart[t] + g_Apart[(size_t)MTOT + t];
}

// =====================================================================
// Segment stats: 64-way partials (8 chunks x 8 batches), then tiny combines
// =====================================================================
__global__ __launch_bounds__(256) void k_segpart(const int* __restrict__ cids) {
    __shared__ float sm[NC * 256];
    __shared__ int   sc[NC * 256];
    const int blk = blockIdx.x, b = blk >> 3, ch = blk & 7, tid = threadIdx.x;
    for (int c = 0; c < NC; c++) { sm[c * 256 + tid] = -3.0e38f; sc[c * 256 + tid] = 0; }
    const int base = b * NTOK + ch * 2048;
    for (int it = 0; it < 8; it++) {
        int t = base + it * 256 + tid;
        int c = clip_cid(cids[t]);
        float v = g_A[t];
        if (v > sm[c * 256 + tid]) sm[c * 256 + tid] = v;
        sc[c * 256 + tid]++;
    }
    __syncthreads();
    if (tid < NC) {
        float m = -3.0e38f; int cnt = 0;
        for (int i = 0; i < 256; i++) { m = fmaxf(m, sm[tid * 256 + i]); cnt += sc[tid * 256 + i]; }
        g_pmax[blk * NC + tid] = m;
        g_pcnt[blk * NC + tid] = cnt;
    }
}
__global__ void k_segfin() {
    int s = threadIdx.x;
    if (s >= NSEG) return;
    int b = s / NC, c = s % NC;
    float m = -3.0e38f; int cnt = 0;
    for (int ch = 0; ch < 8; ch++) {
        m = fmaxf(m, g_pmax[(b * 8 + ch) * NC + c]);
        cnt += g_pcnt[(b * 8 + ch) * NC + c];
    }
    g_segmax[s] = (cnt > 0) ? m : 0.0f;
    g_present[s] = (cnt > 0) ? 1 : 0;
}
__global__ __launch_bounds__(256) void k_segexp(const int* __restrict__ cids) {
    __shared__ float sm[NC * 256];
    __shared__ float fm[NC];
    const int blk = blockIdx.x, b = blk >> 3, ch = blk & 7, tid = threadIdx.x;
    if (tid < NC) fm[tid] = g_segmax[b * NC + tid];
    for (int c = 0; c < NC; c++) sm[c * 256 + tid] = 0.0f;
    __syncthreads();
    const int base = b * NTOK + ch * 2048;
    for (int it = 0; it < 8; it++) {
        int t = base + it * 256 + tid;
        int c = clip_cid(cids[t]);
        sm[c * 256 + tid] += expf(g_A[t] - fm[c]);
    }
    __syncthreads();
    if (tid < NC) {
        float s = 0.0f;
        for (int i = 0; i < 256; i++) s += sm[tid * 256 + i];
        g_psum[blk * NC + tid] = s;
    }
}
__global__ void k_segfin2() {
    int s = threadIdx.x;
    if (s >= NSEG) return;
    int b = s / NC, c = s % NC;
    float d = 0.0f;
    for (int ch = 0; ch < 8; ch++) d += g_psum[(b * 8 + ch) * NC + c];
    g_segden[s] = d;
}
__global__ void k_w(const int* __restrict__ cids) {
    int t = blockIdx.x * blockDim.x + threadIdx.x;
    if (t >= MTOT) return;
    int b = t >> 14;
    int c = clip_cid(cids[t]);
    g_w[t] = expf(g_A[t] - g_segmax[b * NC + c]) / g_segden[b * NC + c];
}

// =====================================================================
// Segment-sum of w-weighted X (hi+lo reconstruct), deterministic partials
// 64 chunks x 8 batches (512 blocks) for better SM coverage
// =====================================================================
__global__ __launch_bounds__(512) void k_accum(const int* __restrict__ cids) {
    __shared__ float acc[NC * 512];
    const int chunk = blockIdx.x, b = blockIdx.y, tid = threadIdx.x;
    for (int i = tid; i < NC * 512; i += 512) acc[i] = 0.0f;
    __syncthreads();
    const int base = b * NTOK + chunk * 256;
    for (int it = 0; it < 256; it++) {
        int row = base + it;
        int c = clip_cid(cids[row]);
        float wv = g_w[row];
        size_t off = (size_t)row * 512 + tid;
        float x = __bfloat162float(g_Xhi[off]) + __bfloat162float(g_Xlo[off]);
        acc[c * 512 + tid] += x * wv;
    }
    __syncthreads();
    float* dst = &g_cfeatPart[(size_t)(b * 64 + chunk) * NC * 512];
    for (int c = 0; c < NC; c++) dst[c * 512 + tid] = acc[c * 512 + tid];
}
__global__ void k_reduceC() {
    int idx = blockIdx.x * blockDim.x + threadIdx.x;
    if (idx >= NSEG * 512) return;
    int b = idx / (NC * 512);
    int off = idx % (NC * 512);
    float s = 0.0f;
#pragma unroll
    for (int j = 0; j < 64; j++) s += g_cfeatPart[(size_t)(b * 64 + j) * NC * 512 + off];
    g_cfeat[idx] = s;
}

// =====================================================================
// Per-cluster-row MLP + gated attention-2 logit (88 rows)
// =====================================================================
__global__ __launch_bounds__(512) void k_intra(
    const float* __restrict__ Wi, const float* __restrict__ bi,
    const float* __restrict__ Wa2, const float* __restrict__ ba2,
    const float* __restrict__ Wb2, const float* __restrict__ bb2,
    const float* __restrict__ Wc2)
{
    __shared__ float cfr[512];
    __shared__ float cf2s[512];
    __shared__ float red[256];
    const int row = blockIdx.x, tid = threadIdx.x;

    cfr[tid] = g_cfeat[row * 512 + tid];
    __syncthreads();
    float s = bi[tid];
    for (int k = 0; k < 512; k++) s = fmaf(cfr[k], Wi[k * 512 + tid], s);
    s = fmaxf(s, 0.0f);
    cf2s[tid] = s;
    g_cf2[row * 512 + tid] = s;
    __syncthreads();
    if (tid < 256) {
        float sa = ba2[tid], sg = bb2[tid];
        for (int k = 0; k < 512; k++) {
            float v = cf2s[k];
            sa = fmaf(v, Wa2[k * 256 + tid], sa);
            sg = fmaf(v, Wb2[k * 256 + tid], sg);
        }
        float a = tanhf(sa);
        float gg = 1.0f / (1.0f + expf(-sg));
        red[tid] = a * gg * Wc2[tid];
    }
    __syncthreads();
    for (int sft = 128; sft > 0; sft >>= 1) {
        if (tid < sft && tid + sft < 256) red[tid] += red[tid + sft];
        __syncthreads();
    }
    if (tid == 0) g_A2[row] = red[0];
}

// =====================================================================
// Per-batch masked softmax over clusters, slide pooling, head MLP
// =====================================================================
__global__ __launch_bounds__(512) void k_final(
    const float* __restrict__ Wint, const float* __restrict__ bint,
    const float* __restrict__ Wcls, const float* __restrict__ bcls,
    float* __restrict__ out)
{
    __shared__ float Wsm[NC];
    __shared__ float slide[512];
    __shared__ float inter[256];
    const int b = blockIdx.x, tid = threadIdx.x;

    if (tid == 0) {
        float av[NC];
        float m = -3.0e38f;
        for (int c = 0; c < NC; c++) {
            av[c] = g_present[b * NC + c] ? g_A2[b * NC + c] : -3.0e38f;
            m = fmaxf(m, av[c]);
        }
        float sden = 0.0f;
        float ex[NC];
        for (int c = 0; c < NC; c++) { ex[c] = expf(av[c] - m); sden += ex[c]; }
        for (int c = 0; c < NC; c++) Wsm[c] = ex[c] / sden;
    }
    __syncthreads();
    float sv = 0.0f;
    for (int c = 0; c < NC; c++) sv = fmaf(Wsm[c], g_cf2[(b * NC + c) * 512 + tid], sv);
    slide[tid] = sv;
    __syncthreads();
    if (tid < 256) {
        float v = bint[tid];
        for (int k = 0; k < 512; k++) v = fmaf(slide[k], Wint[k * 256 + tid], v);
        inter[tid] = fmaxf(v, 0.0f);
    }
    __syncthreads();
    if (tid < 2) {
        float o = bcls[tid];
        for (int k = 0; k < 256; k++) o = fmaf(inter[k], Wcls[k * 2 + tid], o);
        out[b * 2 + tid] = o;
    }
}

// =====================================================================
extern "C" void kernel_launch(void* const* d_in, const int* in_sizes, int n_in,
                              void* d_out, int out_size)
{
    const float* h    = (const float*)d_in[0];
    const int*   cids = (const int*)  d_in[1];
    const float* emb  = (const float*)d_in[2];
    const float* Wf   = (const float*)d_in[3];
    const float* bfu  = (const float*)d_in[4];
    const float* Wa1  = (const float*)d_in[5];
    const float* ba1  = (const float*)d_in[6];
    const float* Wb1  = (const float*)d_in[7];
    const float* bb1  = (const float*)d_in[8];
    const float* Wc1  = (const float*)d_in[9];
    // d_in[10] = bc1: constant shift inside segment softmax -> cancels exactly
    const float* Wi   = (const float*)d_in[11];
    const float* bi   = (const float*)d_in[12];
    const float* Wa2  = (const float*)d_in[13];
    const float* ba2  = (const float*)d_in[14];
    const float* Wb2  = (const float*)d_in[15];
    const float* bb2  = (const float*)d_in[16];
    const float* Wc2  = (const float*)d_in[17];
    // d_in[18] = bc2: cancels in inter-cluster softmax
    const float* Wint = (const float*)d_in[19];
    const float* bint = (const float*)d_in[20];
    const float* Wcls = (const float*)d_in[21];
    const float* bcls = (const float*)d_in[22];
    float* out = (float*)d_out;

    cudaFuncSetAttribute(k_gemm<0>, cudaFuncAttributeMaxDynamicSharedMemorySize, SMEM_REQ);
    cudaFuncSetAttribute(k_gemm<1>, cudaFuncAttributeMaxDynamicSharedMemorySize, SMEM_REQ);

    k_pack_wf <<<512, 256>>>(Wf);
    k_pack_wab<<<512, 256>>>(Wa1, Wb1);
    k_gemm<0> <<<dim3(2, 1024), 512, SMEM_REQ>>>(h, cids, emb, Wf, bfu, nullptr, nullptr, nullptr);
    k_gemm<1> <<<dim3(2, 1024), 512, SMEM_REQ>>>(nullptr, cids, emb, Wf, bfu, ba1, bb1, Wc1);
    k_reduceA <<<(MTOT + 255) / 256, 256>>>();
    k_segpart <<<64, 256>>>(cids);
    k_segfin  <<<1, 128>>>();
    k_segexp  <<<64, 256>>>(cids);
    k_segfin2 <<<1, 128>>>();
    k_w       <<<(MTOT + 255) / 256, 256>>>(cids);
    k_accum   <<<dim3(64, BATCH), 512>>>(cids);
    k_reduceC <<<(NSEG * 512 + 255) / 256, 256>>>();
    k_intra   <<<NSEG, 512>>>(Wi, bi, Wa2, ba2, Wb2, bb2, Wc2);
    k_final   <<<BATCH, 512>>>(Wint, bint, Wcls, bcls, out);
}

// round 13
// speedup vs baseline: 2.2052x; 1.2109x over previous
#include <cuda_runtime.h>
#include <cuda_bf16.h>
#include <math.h>
#include <stdint.h>

// ---------------- problem constants ----------------
#define BATCH 8
#define NTOK  16384
#define MTOT  (BATCH * NTOK)      // 131072 tokens
#define NC    11                  // C+1 clusters
#define NSEG  (BATCH * NC)        // 88

// ---------------- scratch (device globals; no allocations allowed) ----------------
__device__ __nv_bfloat16 g_Xhi[(size_t)MTOT * 512];   // fused features, bf16 hi plane
__device__ __nv_bfloat16 g_Xlo[(size_t)MTOT * 512];   // bf16 lo (residual) plane
__device__ float g_Apart[2 * MTOT];
__device__ float g_A[MTOT];
__device__ float g_w[MTOT];
__device__ float g_pmax[64 * NC];
__device__ int   g_pcnt[64 * NC];
__device__ float g_psum[64 * NC];
__device__ float g_segmax[NSEG];
__device__ float g_segden[NSEG];
__device__ int   g_present[NSEG];
__device__ float g_cfeatPart[BATCH * 64 * NC * 512];
__device__ float g_cfeat[NSEG * 512];
__device__ float g_cf2[NSEG * 512];
__device__ float g_A2[NSEG];
// prepacked weights, K-major [N=512 rows][K=512], hi/lo bf16 split
__device__ __nv_bfloat16 g_Bf_hi[512 * 512];
__device__ __nv_bfloat16 g_Bf_lo[512 * 512];
__device__ __nv_bfloat16 g_Bab_hi[512 * 512];
__device__ __nv_bfloat16 g_Bab_lo[512 * 512];

__device__ __forceinline__ int clip_cid(int c) { return c < 0 ? 0 : (c > 10 ? 10 : c); }

__device__ __forceinline__ uint32_t smu(const void* p) {
    return (uint32_t)__cvta_generic_to_shared(p);
}

// ---------------- sm_90-baseline PTX helpers (valid at .target sm_103) ----------
#define CP_ASYNC16(dst, src) \
    asm volatile("cp.async.cg.shared.global [%0], [%1], 16;" :: "r"(dst), "l"(src))
#define CP_COMMIT() asm volatile("cp.async.commit_group;")
#define CP_WAIT0()  asm volatile("cp.async.wait_group 0;" ::: "memory")
#define CP_WAIT1()  asm volatile("cp.async.wait_group 1;" ::: "memory")

__device__ __forceinline__ void ldsm4(uint32_t* r, uint32_t addr) {
    asm volatile("ldmatrix.sync.aligned.m8n8.x4.shared.b16 {%0,%1,%2,%3}, [%4];"
        : "=r"(r[0]), "=r"(r[1]), "=r"(r[2]), "=r"(r[3]) : "r"(addr));
}
__device__ __forceinline__ void mma4(float* d, const uint32_t* a, const uint32_t* b) {
    asm volatile(
        "mma.sync.aligned.m16n8k16.row.col.f32.bf16.bf16.f32 "
        "{%0,%1,%2,%3}, {%4,%5,%6,%7}, {%8,%9}, {%0,%1,%2,%3};"
        : "+f"(d[0]), "+f"(d[1]), "+f"(d[2]), "+f"(d[3])
        : "r"(a[0]), "r"(a[1]), "r"(a[2]), "r"(a[3]), "r"(b[0]), "r"(b[1]));
}

__device__ __forceinline__ void split2(float a, float b, uint32_t& hi, uint32_t& lo) {
    __nv_bfloat162 hp = __floats2bfloat162_rn(a, b);
    float ra = a - __low2float(hp);
    float rb = b - __high2float(hp);
    __nv_bfloat162 lp = __floats2bfloat162_rn(ra, rb);
    hi = *reinterpret_cast<uint32_t*>(&hp);
    lo = *reinterpret_cast<uint32_t*>(&lp);
}

// ---------------- GEMM tiling ----------------
// BM=128, BN=256, BK=32 (16 k-iters -> half the barriers of BK=16).
// 512 threads = 16 warps (4 m x 4 n), warp tile 32x64.
// Rows padded to 80B (20 words): 8-row ldmatrix phases hit banks
// {0,20,8,28,16,4,24,12}x4 = all 32 banks, conflict-free.
// 3-stage cp.async ring.
#define RSB 80                         // row stride bytes (64 B data + 16 pad)
#define ST_AHI 0
#define ST_ALO 10240                   // 128*80
#define ST_BHI 20480
#define ST_BLO 40960                   // + 256*80
#define STAGE  61440
#define NSTAGES 3
#define NKIT   16                      // 512 / 32
#define OFF_EPI  184320                // 3*STAGE
#define OFF_SRED 193536                // +9216
#define SMEM_REQ 196096                // +2560

// =====================================================================
// HMMA GEMM. EPI=0: fuse (h -> X hi/lo planes, bias+emb-tail+relu)
//            EPI=1: gate (X -> tanh*sigmoid dot Wc1 per-token partials)
// 3-term bf16 split: AhiBhi + AloBhi + AhiBlo.
// =====================================================================
template <int EPI>
__global__ __launch_bounds__(512) void k_gemm(
    const float* __restrict__ hsrc, const int* __restrict__ cids,
    const float* __restrict__ emb, const float* __restrict__ Wf,
    const float* __restrict__ bfu, const float* __restrict__ ba1,
    const float* __restrict__ bb1, const float* __restrict__ Wc1)
{
    extern __shared__ __align__(16) char dsm[];
    const int tid = threadIdx.x;
    const int lane = tid & 31, wid = tid >> 5;
    const int wm = wid >> 2, wn = wid & 3;
    const int colBase = blockIdx.x * 256;
    const int rowBase = blockIdx.y * 128;

    // ---- epilogue constants ----
    float* epi = (float*)(dsm + OFF_EPI);
    if (EPI == 0) {
        if (tid < 256) epi[tid] = bfu[colBase + tid];
        for (int i = tid; i < 2048; i += 512)
            epi[256 + i] = Wf[(512 + (i >> 8)) * 512 + colBase + (i & 255)];
    } else {
        if (tid < 128) {
            epi[tid]       = ba1[colBase / 2 + tid];
            epi[128 + tid] = bb1[colBase / 2 + tid];
            epi[256 + tid] = Wc1[colBase / 2 + tid];
        }
    }

    // ---- per-thread loader indices ----
    const __nv_bfloat16* Bh0 = (EPI == 0) ? g_Bf_hi : g_Bab_hi;
    const __nv_bfloat16* Bl0 = (EPI == 0) ? g_Bf_lo : g_Bab_lo;
    const uint32_t smBase = smu(dsm);

    // B: 256 rows x 4 sixteen-byte chunks per plane = 1024 chunks; 2 per thread
    const int bc0 = tid, bc1 = tid + 512;
    const int rB0 = bc0 >> 2, hB0 = bc0 & 3;
    const int rB1 = bc1 >> 2, hB1 = bc1 & 3;
    const char* srcBh_0 = (const char*)(Bh0 + (size_t)(colBase + rB0) * 512) + hB0 * 16;
    const char* srcBh_1 = (const char*)(Bh0 + (size_t)(colBase + rB1) * 512) + hB1 * 16;
    const char* srcBl_0 = (const char*)(Bl0 + (size_t)(colBase + rB0) * 512) + hB0 * 16;
    const char* srcBl_1 = (const char*)(Bl0 + (size_t)(colBase + rB1) * 512) + hB1 * 16;
    const uint32_t dstB0 = rB0 * RSB + hB0 * 16;
    const uint32_t dstB1 = rB1 * RSB + hB1 * 16;

    // GEMM1 A loader (fp32 h, runtime split): 8 floats/thread
    const int rA = tid >> 2, cq = tid & 3;
    const float* srcA1 = (EPI == 0) ? (hsrc + (size_t)(rowBase + rA) * 512 + cq * 8) : nullptr;
    const uint32_t dstA1off = rA * RSB + cq * 16;
    // GEMM2 A loader (pre-split planes): 128 rows x 4 chunks; same (row,h) both planes
    const int rA2 = tid >> 2, hA2 = tid & 3;
    const char* srcA2h = (const char*)(g_Xhi + (size_t)(rowBase + rA2) * 512) + hA2 * 16;
    const char* srcA2l = (const char*)(g_Xlo + (size_t)(rowBase + rA2) * 512) + hA2 * 16;
    const uint32_t dstA2off = rA2 * RSB + hA2 * 16;

    // ---- ldmatrix addresses (per thread; +kk*32 B selects k-half) ----
    uint32_t offA[2], offB[4];
    {
        int rowAf = wm * 32 + (lane & 15);
        int kAf = (lane >> 4) * 8;
#pragma unroll
        for (int mt = 0; mt < 2; mt++) offA[mt] = (rowAf + mt * 16) * RSB + kAf * 2;
        int rowBf = wn * 64 + (lane & 7) + 8 * (lane >> 4);
        int kBf = ((lane >> 3) & 1) * 8;
#pragma unroll
        for (int nf2 = 0; nf2 < 4; nf2++) offB[nf2] = (rowBf + nf2 * 16) * RSB + kBf * 2;
    }

    // ---- stage loader (cp.async part) ----
    auto load_stage = [&](int sbuf, int ks) {
        uint32_t db = smBase + sbuf * STAGE;
        int bo = ks * 64;   // 32 bf16 = 64 bytes per stage step
        CP_ASYNC16(db + ST_BHI + dstB0, srcBh_0 + bo);
        CP_ASYNC16(db + ST_BHI + dstB1, srcBh_1 + bo);
        CP_ASYNC16(db + ST_BLO + dstB0, srcBl_0 + bo);
        CP_ASYNC16(db + ST_BLO + dstB1, srcBl_1 + bo);
        if (EPI != 0) {
            CP_ASYNC16(db + ST_AHI + dstA2off, srcA2h + bo);
            CP_ASYNC16(db + ST_ALO + dstA2off, srcA2l + bo);
        }
        CP_COMMIT();
    };
    // EPI==0: fp32 A split-store into stage sbuf for k-step ks
    auto store_A1 = [&](int sbuf, float4 v0, float4 v1) {
        uint32_t h0, l0, h1, l1, h2, l2, h3, l3;
        split2(v0.x, v0.y, h0, l0);
        split2(v0.z, v0.w, h1, l1);
        split2(v1.x, v1.y, h2, l2);
        split2(v1.z, v1.w, h3, l3);
        char* dc = dsm + sbuf * STAGE;
        *(uint4*)(dc + ST_AHI + dstA1off) = make_uint4(h0, h1, h2, h3);
        *(uint4*)(dc + ST_ALO + dstA1off) = make_uint4(l0, l1, l2, l3);
    };

    // ---- preamble: stages 0 and 1 ----
#pragma unroll
    for (int s = 0; s < 2; s++) {
        load_stage(s, s);
        if (EPI == 0) {
            float4 v0 = *(const float4*)(srcA1 + s * 32);
            float4 v1 = *(const float4*)(srcA1 + s * 32 + 4);
            store_A1(s, v0, v1);
        }
    }
    CP_WAIT1();          // stage 0 landed
    __syncthreads();

    float acc[2][8][4];
#pragma unroll
    for (int i = 0; i < 2; i++)
#pragma unroll
        for (int j = 0; j < 8; j++)
#pragma unroll
            for (int k = 0; k < 4; k++) acc[i][j][k] = 0.0f;

    // ---- main loop: 16 k-iters of BK=32, 3-stage ring ----
    int buf = 0;
#pragma unroll 1
    for (int ks = 0; ks < NKIT; ks++) {
        int nbuf = buf + 2; if (nbuf >= NSTAGES) nbuf -= NSTAGES;
        float4 av0, av1;
        if (ks < NKIT - 2) {
            load_stage(nbuf, ks + 2);
            if (EPI == 0) {
                av0 = *(const float4*)(srcA1 + (ks + 2) * 32);
                av1 = *(const float4*)(srcA1 + (ks + 2) * 32 + 4);
            }
        }

        // compute on buf (stage ks): two BK=16 sub-steps
        const uint32_t sb = smBase + buf * STAGE;
#pragma unroll
        for (int kk = 0; kk < 2; kk++) {
            const uint32_t ko = kk * 32;   // 16 bf16 = 32 bytes
            uint32_t ah[2][4], al[2][4];
            ldsm4(ah[0], sb + ST_AHI + offA[0] + ko);
            ldsm4(ah[1], sb + ST_AHI + offA[1] + ko);
            ldsm4(al[0], sb + ST_ALO + offA[0] + ko);
            ldsm4(al[1], sb + ST_ALO + offA[1] + ko);
#pragma unroll
            for (int nf2 = 0; nf2 < 4; nf2++) {
                uint32_t bh[4], bl[4];
                ldsm4(bh, sb + ST_BHI + offB[nf2] + ko);
                mma4(acc[0][2 * nf2], ah[0], bh);  mma4(acc[0][2 * nf2 + 1], ah[0], bh + 2);
                mma4(acc[1][2 * nf2], ah[1], bh);  mma4(acc[1][2 * nf2 + 1], ah[1], bh + 2);
                mma4(acc[0][2 * nf2], al[0], bh);  mma4(acc[0][2 * nf2 + 1], al[0], bh + 2);
                mma4(acc[1][2 * nf2], al[1], bh);  mma4(acc[1][2 * nf2 + 1], al[1], bh + 2);
                ldsm4(bl, sb + ST_BLO + offB[nf2] + ko);
                mma4(acc[0][2 * nf2], ah[0], bl);  mma4(acc[0][2 * nf2 + 1], ah[0], bl + 2);
                mma4(acc[1][2 * nf2], ah[1], bl);  mma4(acc[1][2 * nf2 + 1], ah[1], bl + 2);
            }
        }

        if (ks < NKIT - 2 && EPI == 0) store_A1(nbuf, av0, av1);
        if (ks < NKIT - 1) {
            if (ks < NKIT - 2) { CP_WAIT1(); }
            else               { CP_WAIT0(); }
            __syncthreads();
        }
        buf = buf + 1; if (buf >= NSTAGES) buf -= NSTAGES;
    }

    // ---- epilogue ----
    const int q = lane >> 2, p = lane & 3;
    if (EPI == 0) {
#pragma unroll
        for (int mt = 0; mt < 2; mt++)
#pragma unroll
            for (int half = 0; half < 2; half++) {
                int r = rowBase + wm * 32 + mt * 16 + q + 8 * half;
                int cid = clip_cid(cids[r]);
                float ev[8];
#pragma unroll
                for (int e = 0; e < 8; e++) ev[e] = emb[cid * 8 + e];
#pragma unroll
                for (int nf = 0; nf < 8; nf++) {
                    int cl = wn * 64 + nf * 8 + 2 * p;
                    float v0 = acc[mt][nf][2 * half]     + epi[cl];
                    float v1 = acc[mt][nf][2 * half + 1] + epi[cl + 1];
#pragma unroll
                    for (int e = 0; e < 8; e++) {
                        v0 = fmaf(ev[e], epi[256 + e * 256 + cl], v0);
                        v1 = fmaf(ev[e], epi[256 + e * 256 + cl + 1], v1);
                    }
                    v0 = fmaxf(v0, 0.0f);
                    v1 = fmaxf(v1, 0.0f);
                    uint32_t hi, lo;
                    split2(v0, v1, hi, lo);
                    size_t go = (size_t)r * 512 + colBase + cl;
                    *reinterpret_cast<uint32_t*>(g_Xhi + go) = hi;
                    *reinterpret_cast<uint32_t*>(g_Xlo + go) = lo;
                }
            }
    } else {
        float* sred = (float*)(dsm + OFF_SRED);
#pragma unroll
        for (int mt = 0; mt < 2; mt++)
#pragma unroll
            for (int half = 0; half < 2; half++) {
                float s = 0.0f;
#pragma unroll
                for (int nf = 0; nf < 8; nf++) {
                    int jl = wn * 32 + nf * 4 + p;
                    float va = acc[mt][nf][2 * half]     + epi[jl];
                    float vg = acc[mt][nf][2 * half + 1] + epi[128 + jl];
                    float a = tanhf(va);
                    float gg = 1.0f / (1.0f + expf(-vg));
                    s = fmaf(a * gg, epi[256 + jl], s);
                }
                s += __shfl_xor_sync(0xFFFFFFFFu, s, 1);
                s += __shfl_xor_sync(0xFFFFFFFFu, s, 2);
                if (p == 0)
                    sred[(wm * 32 + mt * 16 + q + 8 * half) * 5 + wn] = s;
            }
        __syncthreads();
        if (tid < 128) {
            float t = sred[tid * 5] + sred[tid * 5 + 1] + sred[tid * 5 + 2] + sred[tid * 5 + 3];
            g_Apart[(size_t)blockIdx.x * MTOT + rowBase + tid] = t;
        }
    }
}

// =====================================================================
// Weight prepack: fp32 [K,N] -> bf16 hi/lo K-major [N,K]
// =====================================================================
__global__ __launch_bounds__(256) void k_pack_wf(const float* __restrict__ Wf) {
    int n = blockIdx.x;
    for (int k = threadIdx.x; k < 512; k += 256) {
        float x = Wf[k * 512 + n];
        __nv_bfloat16 hi = __float2bfloat16(x);
        __nv_bfloat16 lo = __float2bfloat16(x - __bfloat162float(hi));
        g_Bf_hi[n * 512 + k] = hi;
        g_Bf_lo[n * 512 + k] = lo;
    }
}
// interleave: row 2p = Wa1 col p, row 2p+1 = Wb1 col p
__global__ __launch_bounds__(256) void k_pack_wab(const float* __restrict__ Wa1,
                                                  const float* __restrict__ Wb1) {
    int n = blockIdx.x;
    int p = n >> 1;
    const float* src = (n & 1) ? Wb1 : Wa1;
    for (int k = threadIdx.x; k < 512; k += 256) {
        float x = src[k * 256 + p];
        __nv_bfloat16 hi = __float2bfloat16(x);
        __nv_bfloat16 lo = __float2bfloat16(x - __bfloat162float(hi));
        g_Bab_hi[n * 512 + k] = hi;
        g_Bab_lo[n * 512 + k] = lo;
    }
}

__global__ void k_reduceA() {
    int t = blockIdx.x * blockDim.x + threadIdx.x;
    if (t >= MTOT) return;
    g_A[t] = g_Apart[t] + g_Apart[(size_t)MTOT + t];
}

// =====================================================================
// Segment stats: 64-way partials (8 chunks x 8 batches), then tiny combines
// =====================================================================
__global__ __launch_bounds__(256) void k_segpart(const int* __restrict__ cids) {
    __shared__ float sm[NC * 256];
    __shared__ int   sc[NC * 256];
    const int blk = blockIdx.x, b = blk >> 3, ch = blk & 7, tid = threadIdx.x;
    for (int c = 0; c < NC; c++) { sm[c * 256 + tid] = -3.0e38f; sc[c * 256 + tid] = 0; }
    const int base = b * NTOK + ch * 2048;
    for (int it = 0; it < 8; it++) {
        int t = base + it * 256 + tid;
        int c = clip_cid(cids[t]);
        float v = g_A[t];
        if (v > sm[c * 256 + tid]) sm[c * 256 + tid] = v;
        sc[c * 256 + tid]++;
    }
    __syncthreads();
    if (tid < NC) {
        float m = -3.0e38f; int cnt = 0;
        for (int i = 0; i < 256; i++) { m = fmaxf(m, sm[tid * 256 + i]); cnt += sc[tid * 256 + i]; }
        g_pmax[blk * NC + tid] = m;
        g_pcnt[blk * NC + tid] = cnt;
    }
}
__global__ void k_segfin() {
    int s = threadIdx.x;
    if (s >= NSEG) return;
    int b = s / NC, c = s % NC;
    float m = -3.0e38f; int cnt = 0;
    for (int ch = 0; ch < 8; ch++) {
        m = fmaxf(m, g_pmax[(b * 8 + ch) * NC + c]);
        cnt += g_pcnt[(b * 8 + ch) * NC + c];
    }
    g_segmax[s] = (cnt > 0) ? m : 0.0f;
    g_present[s] = (cnt > 0) ? 1 : 0;
}
__global__ __launch_bounds__(256) void k_segexp(const int* __restrict__ cids) {
    __shared__ float sm[NC * 256];
    __shared__ float fm[NC];
    const int blk = blockIdx.x, b = blk >> 3, ch = blk & 7, tid = threadIdx.x;
    if (tid < NC) fm[tid] = g_segmax[b * NC + tid];
    for (int c = 0; c < NC; c++) sm[c * 256 + tid] = 0.0f;
    __syncthreads();
    const int base = b * NTOK + ch * 2048;
    for (int it = 0; it < 8; it++) {
        int t = base + it * 256 + tid;
        int c = clip_cid(cids[t]);
        sm[c * 256 + tid] += expf(g_A[t] - fm[c]);
    }
    __syncthreads();
    if (tid < NC) {
        float s = 0.0f;
        for (int i = 0; i < 256; i++) s += sm[tid * 256 + i];
        g_psum[blk * NC + tid] = s;
    }
}
__global__ void k_segfin2() {
    int s = threadIdx.x;
    if (s >= NSEG) return;
    int b = s / NC, c = s % NC;
    float d = 0.0f;
    for (int ch = 0; ch < 8; ch++) d += g_psum[(b * 8 + ch) * NC + c];
    g_segden[s] = d;
}
__global__ void k_w(const int* __restrict__ cids) {
    int t = blockIdx.x * blockDim.x + threadIdx.x;
    if (t >= MTOT) return;
    int b = t >> 14;
    int c = clip_cid(cids[t]);
    g_w[t] = expf(g_A[t] - g_segmax[b * NC + c]) / g_segden[b * NC + c];
}

// =====================================================================
// Segment-sum of w-weighted X (hi+lo reconstruct), deterministic partials
// 64 chunks x 8 batches (512 blocks) for better SM coverage
// =====================================================================
__global__ __launch_bounds__(512) void k_accum(const int* __restrict__ cids) {
    __shared__ float acc[NC * 512];
    const int chunk = blockIdx.x, b = blockIdx.y, tid = threadIdx.x;
    for (int i = tid; i < NC * 512; i += 512) acc[i] = 0.0f;
    __syncthreads();
    const int base = b * NTOK + chunk * 256;
    for (int it = 0; it < 256; it++) {
        int row = base + it;
        int c = clip_cid(cids[row]);
        float wv = g_w[row];
        size_t off = (size_t)row * 512 + tid;
        float x = __bfloat162float(g_Xhi[off]) + __bfloat162float(g_Xlo[off]);
        acc[c * 512 + tid] += x * wv;
    }
    __syncthreads();
    float* dst = &g_cfeatPart[(size_t)(b * 64 + chunk) * NC * 512];
    for (int c = 0; c < NC; c++) dst[c * 512 + tid] = acc[c * 512 + tid];
}
__global__ void k_reduceC() {
    int idx = blockIdx.x * blockDim.x + threadIdx.x;
    if (idx >= NSEG * 512) return;
    int b = idx / (NC * 512);
    int off = idx % (NC * 512);
    float s = 0.0f;
#pragma unroll
    for (int j = 0; j < 64; j++) s += g_cfeatPart[(size_t)(b * 64 + j) * NC * 512 + off];
    g_cfeat[idx] = s;
}

// =====================================================================
// Per-cluster-row MLP + gated attention-2 logit (88 rows)
// =====================================================================
__global__ __launch_bounds__(512) void k_intra(
    const float* __restrict__ Wi, const float* __restrict__ bi,
    const float* __restrict__ Wa2, const float* __restrict__ ba2,
    const float* __restrict__ Wb2, const float* __restrict__ bb2,
    const float* __restrict__ Wc2)
{
    __shared__ float cfr[512];
    __shared__ float cf2s[512];
    __shared__ float red[256];
    const int row = blockIdx.x, tid = threadIdx.x;

    cfr[tid] = g_cfeat[row * 512 + tid];
    __syncthreads();
    float s = bi[tid];
    for (int k = 0; k < 512; k++) s = fmaf(cfr[k], Wi[k * 512 + tid], s);
    s = fmaxf(s, 0.0f);
    cf2s[tid] = s;
    g_cf2[row * 512 + tid] = s;
    __syncthreads();
    if (tid < 256) {
        float sa = ba2[tid], sg = bb2[tid];
        for (int k = 0; k < 512; k++) {
            float v = cf2s[k];
            sa = fmaf(v, Wa2[k * 256 + tid], sa);
            sg = fmaf(v, Wb2[k * 256 + tid], sg);
        }
        float a = tanhf(sa);
        float gg = 1.0f / (1.0f + expf(-sg));
        red[tid] = a * gg * Wc2[tid];
    }
    __syncthreads();
    for (int sft = 128; sft > 0; sft >>= 1) {
        if (tid < sft && tid + sft < 256) red[tid] += red[tid + sft];
        __syncthreads();
    }
    if (tid == 0) g_A2[row] = red[0];
}

// =====================================================================
// Per-batch masked softmax over clusters, slide pooling, head MLP
// =====================================================================
__global__ __launch_bounds__(512) void k_final(
    const float* __restrict__ Wint, const float* __restrict__ bint,
    const float* __restrict__ Wcls, const float* __restrict__ bcls,
    float* __restrict__ out)
{
    __shared__ float Wsm[NC];
    __shared__ float slide[512];
    __shared__ float inter[256];
    const int b = blockIdx.x, tid = threadIdx.x;

    if (tid == 0) {
        float av[NC];
        float m = -3.0e38f;
        for (int c = 0; c < NC; c++) {
            av[c] = g_present[b * NC + c] ? g_A2[b * NC + c] : -3.0e38f;
            m = fmaxf(m, av[c]);
        }
        float sden = 0.0f;
        float ex[NC];
        for (int c = 0; c < NC; c++) { ex[c] = expf(av[c] - m); sden += ex[c]; }
        for (int c = 0; c < NC; c++) Wsm[c] = ex[c] / sden;
    }
    __syncthreads();
    float sv = 0.0f;
    for (int c = 0; c < NC; c++) sv = fmaf(Wsm[c], g_cf2[(b * NC + c) * 512 + tid], sv);
    slide[tid] = sv;
    __syncthreads();
    if (tid < 256) {
        float v = bint[tid];
        for (int k = 0; k < 512; k++) v = fmaf(slide[k], Wint[k * 256 + tid], v);
        inter[tid] = fmaxf(v, 0.0f);
    }
    __syncthreads();
    if (tid < 2) {
        float o = bcls[tid];
        for (int k = 0; k < 256; k++) o = fmaf(inter[k], Wcls[k * 2 + tid], o);
        out[b * 2 + tid] = o;
    }
}

// =====================================================================
extern "C" void kernel_launch(void* const* d_in, const int* in_sizes, int n_in,
                              void* d_out, int out_size)
{
    const float* h    = (const float*)d_in[0];
    const int*   cids = (const int*)  d_in[1];
    const float* emb  = (const float*)d_in[2];
    const float* Wf   = (const float*)d_in[3];
    const float* bfu  = (const float*)d_in[4];
    const float* Wa1  = (const float*)d_in[5];
    const float* ba1  = (const float*)d_in[6];
    const float* Wb1  = (const float*)d_in[7];
    const float* bb1  = (const float*)d_in[8];
    const float* Wc1  = (const float*)d_in[9];
    // d_in[10] = bc1: constant shift inside segment softmax -> cancels exactly
    const float* Wi   = (const float*)d_in[11];
    const float* bi   = (const float*)d_in[12];
    const float* Wa2  = (const float*)d_in[13];
    const float* ba2  = (const float*)d_in[14];
    const float* Wb2  = (const float*)d_in[15];
    const float* bb2  = (const float*)d_in[16];
    const float* Wc2  = (const float*)d_in[17];
    // d_in[18] = bc2: cancels in inter-cluster softmax
    const float* Wint = (const float*)d_in[19];
    const float* bint = (const float*)d_in[20];
    const float* Wcls = (const float*)d_in[21];
    const float* bcls = (const float*)d_in[22];
    float* out = (float*)d_out;

    cudaFuncSetAttribute(k_gemm<0>, cudaFuncAttributeMaxDynamicSharedMemorySize, SMEM_REQ);
    cudaFuncSetAttribute(k_gemm<1>, cudaFuncAttributeMaxDynamicSharedMemorySize, SMEM_REQ);

    k_pack_wf <<<512, 256>>>(Wf);
    k_pack_wab<<<512, 256>>>(Wa1, Wb1);
    k_gemm<0> <<<dim3(2, 1024), 512, SMEM_REQ>>>(h, cids, emb, Wf, bfu, nullptr, nullptr, nullptr);
    k_gemm<1> <<<dim3(2, 1024), 512, SMEM_REQ>>>(nullptr, cids, emb, Wf, bfu, ba1, bb1, Wc1);
    k_reduceA <<<(MTOT + 255) / 256, 256>>>();
    k_segpart <<<64, 256>>>(cids);
    k_segfin  <<<1, 128>>>();
    k_segexp  <<<64, 256>>>(cids);
    k_segfin2 <<<1, 128>>>();
    k_w       <<<(MTOT + 255) / 256, 256>>>(cids);
    k_accum   <<<dim3(64, BATCH), 512>>>(cids);
    k_reduceC <<<(NSEG * 512 + 255) / 256, 256>>>();
    k_intra   <<<NSEG, 512>>>(Wi, bi, Wa2, ba2, Wb2, bb2, Wc2);
    k_final   <<<BATCH, 512>>>(Wint, bint, Wcls, bcls, out);
}

// round 15
// speedup vs baseline: 2.2477x; 1.0193x over previous
#include <cuda_runtime.h>
#include <cuda_bf16.h>
#include <math.h>
#include <stdint.h>

// ---------------- problem constants ----------------
#define BATCH 8
#define NTOK  16384
#define MTOT  (BATCH * NTOK)      // 131072 tokens
#define NC    11                  // C+1 clusters
#define NSEG  (BATCH * NC)        // 88

// ---------------- scratch (device globals; no allocations allowed) ----------------
__device__ __nv_bfloat16 g_Xhi[(size_t)MTOT * 512];   // fused features, bf16 hi plane
__device__ __nv_bfloat16 g_Xlo[(size_t)MTOT * 512];   // bf16 lo (residual) plane
__device__ float g_Apart[2 * MTOT];
__device__ float g_A[MTOT];
__device__ float g_w[MTOT];
__device__ float g_pmax[64 * NC];
__device__ int   g_pcnt[64 * NC];
__device__ float g_psum[64 * NC];
__device__ float g_segmax[NSEG];
__device__ float g_segden[NSEG];
__device__ int   g_present[NSEG];
__device__ float g_cfeatPart[BATCH * 64 * NC * 512];
__device__ float g_cfeat[NSEG * 512];
__device__ float g_cf2[NSEG * 512];
__device__ float g_A2[NSEG];
// prepacked weights, K-major [N=512 rows][K=512], hi/lo bf16 split
__device__ __nv_bfloat16 g_Bf_hi[512 * 512];
__device__ __nv_bfloat16 g_Bf_lo[512 * 512];
__device__ __nv_bfloat16 g_Bab_hi[512 * 512];
__device__ __nv_bfloat16 g_Bab_lo[512 * 512];

__device__ __forceinline__ int clip_cid(int c) { return c < 0 ? 0 : (c > 10 ? 10 : c); }

__device__ __forceinline__ uint32_t smu(const void* p) {
    return (uint32_t)__cvta_generic_to_shared(p);
}

// ---------------- sm_90-baseline PTX helpers (valid at .target sm_103) ----------
#define CP_ASYNC16(dst, src) \
    asm volatile("cp.async.cg.shared.global [%0], [%1], 16;" :: "r"(dst), "l"(src))
#define CP_COMMIT() asm volatile("cp.async.commit_group;")
#define CP_WAIT0()  asm volatile("cp.async.wait_group 0;" ::: "memory")

__device__ __forceinline__ void ldsm4(uint32_t* r, uint32_t addr) {
    asm volatile("ldmatrix.sync.aligned.m8n8.x4.shared.b16 {%0,%1,%2,%3}, [%4];"
        : "=r"(r[0]), "=r"(r[1]), "=r"(r[2]), "=r"(r[3]) : "r"(addr));
}
__device__ __forceinline__ void mma4(float* d, const uint32_t* a, const uint32_t* b) {
    asm volatile(
        "mma.sync.aligned.m16n8k16.row.col.f32.bf16.bf16.f32 "
        "{%0,%1,%2,%3}, {%4,%5,%6,%7}, {%8,%9}, {%0,%1,%2,%3};"
        : "+f"(d[0]), "+f"(d[1]), "+f"(d[2]), "+f"(d[3])
        : "r"(a[0]), "r"(a[1]), "r"(a[2]), "r"(a[3]), "r"(b[0]), "r"(b[1]));
}

__device__ __forceinline__ void split2(float a, float b, uint32_t& hi, uint32_t& lo) {
    __nv_bfloat162 hp = __floats2bfloat162_rn(a, b);
    float ra = a - __low2float(hp);
    float rb = b - __high2float(hp);
    __nv_bfloat162 lp = __floats2bfloat162_rn(ra, rb);
    hi = *reinterpret_cast<uint32_t*>(&hp);
    lo = *reinterpret_cast<uint32_t*>(&lp);
}

// ---------------- GEMM tiling ----------------
// BM=128, BN=256, BK=64 (8 k-iters -> half the barriers of BK=32).
// 512 threads = 16 warps (4 m x 4 n), warp tile 32x64.
// Rows padded to 144B (36 words): 8-row ldmatrix phases start at banks 4r,
// each row spans banks [4r, 4r+3] -> all 32 banks exactly once, conflict-free.
// 2-stage cp.async (R12 proved extra stages are neutral: loads fully hidden).
#define RSB 144                        // row stride bytes (128 B data + 16 pad)
#define ST_AHI 0
#define ST_ALO 18432                   // 128*144
#define ST_BHI 36864
#define ST_BLO 73728                   // + 256*144
#define STAGE  110592
#define NKIT   8                       // 512 / 64
#define OFF_EPI  221184                // 2*STAGE
#define OFF_SRED (OFF_EPI + 2048)      // EPI=1 uses epi[0..383] only; sred fits after
#define SMEM_REQ 230400                // 2*STAGE + 9216

// =====================================================================
// HMMA GEMM. EPI=0: fuse (h -> X hi/lo planes, bias+emb-tail+relu)
//            EPI=1: gate (X -> tanh*sigmoid dot Wc1 per-token partials)
// 3-term bf16 split: AhiBhi + AloBhi + AhiBlo.
// =====================================================================
template <int EPI>
__global__ __launch_bounds__(512) void k_gemm(
    const float* __restrict__ hsrc, const int* __restrict__ cids,
    const float* __restrict__ emb, const float* __restrict__ Wf,
    const float* __restrict__ bfu, const float* __restrict__ ba1,
    const float* __restrict__ bb1, const float* __restrict__ Wc1)
{
    extern __shared__ __align__(16) char dsm[];
    const int tid = threadIdx.x;
    const int lane = tid & 31, wid = tid >> 5;
    const int wm = wid >> 2, wn = wid & 3;
    const int colBase = blockIdx.x * 256;
    const int rowBase = blockIdx.y * 128;

    // ---- epilogue constants ----
    float* epi = (float*)(dsm + OFF_EPI);
    if (EPI == 0) {
        if (tid < 256) epi[tid] = bfu[colBase + tid];
        for (int i = tid; i < 2048; i += 512)
            epi[256 + i] = Wf[(512 + (i >> 8)) * 512 + colBase + (i & 255)];
    } else {
        if (tid < 128) {
            epi[tid]       = ba1[colBase / 2 + tid];
            epi[128 + tid] = bb1[colBase / 2 + tid];
            epi[256 + tid] = Wc1[colBase / 2 + tid];
        }
    }

    // ---- per-thread loader indices ----
    const __nv_bfloat16* Bh0 = (EPI == 0) ? g_Bf_hi : g_Bab_hi;
    const __nv_bfloat16* Bl0 = (EPI == 0) ? g_Bf_lo : g_Bab_lo;
    const uint32_t smBase = smu(dsm);

    // B: per plane 256 rows x 8 chunks(16B) = 2048; x2 planes = 4096; 8/thread
    const char* srcBh[4]; const char* srcBl[4]; uint32_t dstB[4];
#pragma unroll
    for (int i = 0; i < 4; i++) {
        int c = tid + 512 * i;
        int rB = c >> 3, hB = c & 7;
        srcBh[i] = (const char*)(Bh0 + (size_t)(colBase + rB) * 512) + hB * 16;
        srcBl[i] = (const char*)(Bl0 + (size_t)(colBase + rB) * 512) + hB * 16;
        dstB[i] = rB * RSB + hB * 16;
    }

    // GEMM1 A loader (fp32 h, runtime split): 16 floats/thread
    const int rA = tid >> 2, cq = tid & 3;
    const float* srcA1 = (EPI == 0) ? (hsrc + (size_t)(rowBase + rA) * 512 + cq * 16) : nullptr;
    const uint32_t dstA1off = rA * RSB + cq * 32;
    // GEMM2 A loader (pre-split planes): per plane 128 rows x 8 chunks = 1024; 2/thread
    const char* srcA2h[2]; const char* srcA2l[2]; uint32_t dstA2[2];
#pragma unroll
    for (int i = 0; i < 2; i++) {
        int c = tid + 512 * i;
        int rr = c >> 3, hh = c & 7;
        srcA2h[i] = (const char*)(g_Xhi + (size_t)(rowBase + rr) * 512) + hh * 16;
        srcA2l[i] = (const char*)(g_Xlo + (size_t)(rowBase + rr) * 512) + hh * 16;
        dstA2[i] = rr * RSB + hh * 16;
    }

    // ---- ldmatrix addresses (per thread; +kk*32 B selects k-quarter) ----
    uint32_t offA[2], offB[4];
    {
        int rowAf = wm * 32 + (lane & 15);
        int kAf = (lane >> 4) * 8;
#pragma unroll
        for (int mt = 0; mt < 2; mt++) offA[mt] = (rowAf + mt * 16) * RSB + kAf * 2;
        int rowBf = wn * 64 + (lane & 7) + 8 * (lane >> 4);
        int kBf = ((lane >> 3) & 1) * 8;
#pragma unroll
        for (int nf2 = 0; nf2 < 4; nf2++) offB[nf2] = (rowBf + nf2 * 16) * RSB + kBf * 2;
    }

    // ---- stage loader (cp.async part); bo = ks*128 bytes (64 bf16) ----
    auto load_stage = [&](int sbuf, int ks) {
        uint32_t db = smBase + sbuf * STAGE;
        int bo = ks * 128;
#pragma unroll
        for (int i = 0; i < 4; i++) {
            CP_ASYNC16(db + ST_BHI + dstB[i], srcBh[i] + bo);
            CP_ASYNC16(db + ST_BLO + dstB[i], srcBl[i] + bo);
        }
        if (EPI != 0) {
#pragma unroll
            for (int i = 0; i < 2; i++) {
                CP_ASYNC16(db + ST_AHI + dstA2[i], srcA2h[i] + bo);
                CP_ASYNC16(db + ST_ALO + dstA2[i], srcA2l[i] + bo);
            }
        }
        CP_COMMIT();
    };
    // EPI==0: fp32 A split-store (16 floats) into stage sbuf
    auto store_A1 = [&](int sbuf, const float4* v) {
        uint32_t h[8], l[8];
#pragma unroll
        for (int q = 0; q < 4; q++) {
            split2(v[q].x, v[q].y, h[2 * q], l[2 * q]);
            split2(v[q].z, v[q].w, h[2 * q + 1], l[2 * q + 1]);
        }
        char* dc = dsm + sbuf * STAGE;
        *(uint4*)(dc + ST_AHI + dstA1off)      = make_uint4(h[0], h[1], h[2], h[3]);
        *(uint4*)(dc + ST_AHI + dstA1off + 16) = make_uint4(h[4], h[5], h[6], h[7]);
        *(uint4*)(dc + ST_ALO + dstA1off)      = make_uint4(l[0], l[1], l[2], l[3]);
        *(uint4*)(dc + ST_ALO + dstA1off + 16) = make_uint4(l[4], l[5], l[6], l[7]);
    };

    // ---- preamble: stage 0 ----
    {
        load_stage(0, 0);
        if (EPI == 0) {
            float4 v[4];
#pragma unroll
            for (int q = 0; q < 4; q++) v[q] = *(const float4*)(srcA1 + q * 4);
            store_A1(0, v);
        }
        CP_WAIT0();
    }
    __syncthreads();

    float acc[2][8][4];
#pragma unroll
    for (int i = 0; i < 2; i++)
#pragma unroll
        for (int j = 0; j < 8; j++)
#pragma unroll
            for (int k = 0; k < 4; k++) acc[i][j][k] = 0.0f;

    // ---- main loop: 8 k-iters of BK=64, double buffered ----
    int buf = 0;
#pragma unroll 1
    for (int ks = 0; ks < NKIT; ks++) {
        float4 av[4];
        if (ks < NKIT - 1) {
            load_stage(buf ^ 1, ks + 1);
            if (EPI == 0) {
#pragma unroll
                for (int q = 0; q < 4; q++)
                    av[q] = *(const float4*)(srcA1 + (ks + 1) * 64 + q * 4);
            }
        }

        // compute on buf (stage ks): four BK=16 sub-steps
        const uint32_t sb = smBase + buf * STAGE;
#pragma unroll
        for (int kk = 0; kk < 4; kk++) {
            const uint32_t ko = kk * 32;   // 16 bf16 = 32 bytes
            uint32_t ah[2][4], al[2][4];
            ldsm4(ah[0], sb + ST_AHI + offA[0] + ko);
            ldsm4(ah[1], sb + ST_AHI + offA[1] + ko);
            ldsm4(al[0], sb + ST_ALO + offA[0] + ko);
            ldsm4(al[1], sb + ST_ALO + offA[1] + ko);
#pragma unroll
            for (int nf2 = 0; nf2 < 4; nf2++) {
                uint32_t bh[4], bl[4];
                ldsm4(bh, sb + ST_BHI + offB[nf2] + ko);
                mma4(acc[0][2 * nf2], ah[0], bh);  mma4(acc[0][2 * nf2 + 1], ah[0], bh + 2);
                mma4(acc[1][2 * nf2], ah[1], bh);  mma4(acc[1][2 * nf2 + 1], ah[1], bh + 2);
                mma4(acc[0][2 * nf2], al[0], bh);  mma4(acc[0][2 * nf2 + 1], al[0], bh + 2);
                mma4(acc[1][2 * nf2], al[1], bh);  mma4(acc[1][2 * nf2 + 1], al[1], bh + 2);
                ldsm4(bl, sb + ST_BLO + offB[nf2] + ko);
                mma4(acc[0][2 * nf2], ah[0], bl);  mma4(acc[0][2 * nf2 + 1], ah[0], bl + 2);
                mma4(acc[1][2 * nf2], ah[1], bl);  mma4(acc[1][2 * nf2 + 1], ah[1], bl + 2);
            }
        }

        if (ks < NKIT - 1) {
            if (EPI == 0) store_A1(buf ^ 1, av);
            CP_WAIT0();
            __syncthreads();
        }
        buf ^= 1;
    }

    // ---- epilogue ----
    const int q = lane >> 2, p = lane & 3;
    if (EPI == 0) {
#pragma unroll
        for (int mt = 0; mt < 2; mt++)
#pragma unroll
            for (int half = 0; half < 2; half++) {
                int r = rowBase + wm * 32 + mt * 16 + q + 8 * half;
                int cid = clip_cid(cids[r]);
                float ev[8];
#pragma unroll
                for (int e = 0; e < 8; e++) ev[e] = emb[cid * 8 + e];
#pragma unroll
                for (int nf = 0; nf < 8; nf++) {
                    int cl = wn * 64 + nf * 8 + 2 * p;
                    float v0 = acc[mt][nf][2 * half]     + epi[cl];
                    float v1 = acc[mt][nf][2 * half + 1] + epi[cl + 1];
#pragma unroll
                    for (int e = 0; e < 8; e++) {
                        v0 = fmaf(ev[e], epi[256 + e * 256 + cl], v0);
                        v1 = fmaf(ev[e], epi[256 + e * 256 + cl + 1], v1);
                    }
                    v0 = fmaxf(v0, 0.0f);
                    v1 = fmaxf(v1, 0.0f);
                    uint32_t hi, lo;
                    split2(v0, v1, hi, lo);
                    size_t go = (size_t)r * 512 + colBase + cl;
                    *reinterpret_cast<uint32_t*>(g_Xhi + go) = hi;
                    *reinterpret_cast<uint32_t*>(g_Xlo + go) = lo;
                }
            }
    } else {
        float* sred = (float*)(dsm + OFF_SRED);
#pragma unroll
        for (int mt = 0; mt < 2; mt++)
#pragma unroll
            for (int half = 0; half < 2; half++) {
                float s = 0.0f;
#pragma unroll
                for (int nf = 0; nf < 8; nf++) {
                    int jl = wn * 32 + nf * 4 + p;
                    float va = acc[mt][nf][2 * half]     + epi[jl];
                    float vg = acc[mt][nf][2 * half + 1] + epi[128 + jl];
                    float a = tanhf(va);
                    float gg = 1.0f / (1.0f + expf(-vg));
                    s = fmaf(a * gg, epi[256 + jl], s);
                }
                s += __shfl_xor_sync(0xFFFFFFFFu, s, 1);
                s += __shfl_xor_sync(0xFFFFFFFFu, s, 2);
                if (p == 0)
                    sred[(wm * 32 + mt * 16 + q + 8 * half) * 5 + wn] = s;
            }
        __syncthreads();
        if (tid < 128) {
            float t = sred[tid * 5] + sred[tid * 5 + 1] + sred[tid * 5 + 2] + sred[tid * 5 + 3];
            g_Apart[(size_t)blockIdx.x * MTOT + rowBase + tid] = t;
        }
    }
}

// =====================================================================
// Weight prepack: fp32 [K,N] -> bf16 hi/lo K-major [N,K]
// =====================================================================
__global__ __launch_bounds__(256) void k_pack_wf(const float* __restrict__ Wf) {
    int n = blockIdx.x;
    for (int k = threadIdx.x; k < 512; k += 256) {
        float x = Wf[k * 512 + n];
        __nv_bfloat16 hi = __float2bfloat16(x);
        __nv_bfloat16 lo = __float2bfloat16(x - __bfloat162float(hi));
        g_Bf_hi[n * 512 + k] = hi;
        g_Bf_lo[n * 512 + k] = lo;
    }
}
// interleave: row 2p = Wa1 col p, row 2p+1 = Wb1 col p
__global__ __launch_bounds__(256) void k_pack_wab(const float* __restrict__ Wa1,
                                                  const float* __restrict__ Wb1) {
    int n = blockIdx.x;
    int p = n >> 1;
    const float* src = (n & 1) ? Wb1 : Wa1;
    for (int k = threadIdx.x; k < 512; k += 256) {
        float x = src[k * 256 + p];
        __nv_bfloat16 hi = __float2bfloat16(x);
        __nv_bfloat16 lo = __float2bfloat16(x - __bfloat162float(hi));
        g_Bab_hi[n * 512 + k] = hi;
        g_Bab_lo[n * 512 + k] = lo;
    }
}

__global__ void k_reduceA() {
    int t = blockIdx.x * blockDim.x + threadIdx.x;
    if (t >= MTOT) return;
    g_A[t] = g_Apart[t] + g_Apart[(size_t)MTOT + t];
}

// =====================================================================
// Segment stats: 64-way partials (8 chunks x 8 batches), then tiny combines
// =====================================================================
__global__ __launch_bounds__(256) void k_segpart(const int* __restrict__ cids) {
    __shared__ float sm[NC * 256];
    __shared__ int   sc[NC * 256];
    const int blk = blockIdx.x, b = blk >> 3, ch = blk & 7, tid = threadIdx.x;
    for (int c = 0; c < NC; c++) { sm[c * 256 + tid] = -3.0e38f; sc[c * 256 + tid] = 0; }
    const int base = b * NTOK + ch * 2048;
    for (int it = 0; it < 8; it++) {
        int t = base + it * 256 + tid;
        int c = clip_cid(cids[t]);
        float v = g_A[t];
        if (v > sm[c * 256 + tid]) sm[c * 256 + tid] = v;
        sc[c * 256 + tid]++;
    }
    __syncthreads();
    if (tid < NC) {
        float m = -3.0e38f; int cnt = 0;
        for (int i = 0; i < 256; i++) { m = fmaxf(m, sm[tid * 256 + i]); cnt += sc[tid * 256 + i]; }
        g_pmax[blk * NC + tid] = m;
        g_pcnt[blk * NC + tid] = cnt;
    }
}
__global__ void k_segfin() {
    int s = threadIdx.x;
    if (s >= NSEG) return;
    int b = s / NC, c = s % NC;
    float m = -3.0e38f; int cnt = 0;
    for (int ch = 0; ch < 8; ch++) {
        m = fmaxf(m, g_pmax[(b * 8 + ch) * NC + c]);
        cnt += g_pcnt[(b * 8 + ch) * NC + c];
    }
    g_segmax[s] = (cnt > 0) ? m : 0.0f;
    g_present[s] = (cnt > 0) ? 1 : 0;
}
__global__ __launch_bounds__(256) void k_segexp(const int* __restrict__ cids) {
    __shared__ float sm[NC * 256];
    __shared__ float fm[NC];
    const int blk = blockIdx.x, b = blk >> 3, ch = blk & 7, tid = threadIdx.x;
    if (tid < NC) fm[tid] = g_segmax[b * NC + tid];
    for (int c = 0; c < NC; c++) sm[c * 256 + tid] = 0.0f;
    __syncthreads();
    const int base = b * NTOK + ch * 2048;
    for (int it = 0; it < 8; it++) {
        int t = base + it * 256 + tid;
        int c = clip_cid(cids[t]);
        sm[c * 256 + tid] += expf(g_A[t] - fm[c]);
    }
    __syncthreads();
    if (tid < NC) {
        float s = 0.0f;
        for (int i = 0; i < 256; i++) s += sm[tid * 256 + i];
        g_psum[blk * NC + tid] = s;
    }
}
__global__ void k_segfin2() {
    int s = threadIdx.x;
    if (s >= NSEG) return;
    int b = s / NC, c = s % NC;
    float d = 0.0f;
    for (int ch = 0; ch < 8; ch++) d += g_psum[(b * 8 + ch) * NC + c];
    g_segden[s] = d;
}
__global__ void k_w(const int* __restrict__ cids) {
    int t = blockIdx.x * blockDim.x + threadIdx.x;
    if (t >= MTOT) return;
    int b = t >> 14;
    int c = clip_cid(cids[t]);
    g_w[t] = expf(g_A[t] - g_segmax[b * NC + c]) / g_segden[b * NC + c];
}

// =====================================================================
// Segment-sum of w-weighted X (hi+lo reconstruct), deterministic partials
// 64 chunks x 8 batches (512 blocks) for better SM coverage
// =====================================================================
__global__ __launch_bounds__(512) void k_accum(const int* __restrict__ cids) {
    __shared__ float acc[NC * 512];
    const int chunk = blockIdx.x, b = blockIdx.y, tid = threadIdx.x;
    for (int i = tid; i < NC * 512; i += 512) acc[i] = 0.0f;
    __syncthreads();
    const int base = b * NTOK + chunk * 256;
    for (int it = 0; it < 256; it++) {
        int row = base + it;
        int c = clip_cid(cids[row]);
        float wv = g_w[row];
        size_t off = (size_t)row * 512 + tid;
        float x = __bfloat162float(g_Xhi[off]) + __bfloat162float(g_Xlo[off]);
        acc[c * 512 + tid] += x * wv;
    }
    __syncthreads();
    float* dst = &g_cfeatPart[(size_t)(b * 64 + chunk) * NC * 512];
    for (int c = 0; c < NC; c++) dst[c * 512 + tid] = acc[c * 512 + tid];
}
__global__ void k_reduceC() {
    int idx = blockIdx.x * blockDim.x + threadIdx.x;
    if (idx >= NSEG * 512) return;
    int b = idx / (NC * 512);
    int off = idx % (NC * 512);
    float s = 0.0f;
#pragma unroll
    for (int j = 0; j < 64; j++) s += g_cfeatPart[(size_t)(b * 64 + j) * NC * 512 + off];
    g_cfeat[idx] = s;
}

// =====================================================================
// Per-cluster-row MLP + gated attention-2 logit (88 rows)
// =====================================================================
__global__ __launch_bounds__(512) void k_intra(
    const float* __restrict__ Wi, const float* __restrict__ bi,
    const float* __restrict__ Wa2, const float* __restrict__ ba2,
    const float* __restrict__ Wb2, const float* __restrict__ bb2,
    const float* __restrict__ Wc2)
{
    __shared__ float cfr[512];
    __shared__ float cf2s[512];
    __shared__ float red[256];
    const int row = blockIdx.x, tid = threadIdx.x;

    cfr[tid] = g_cfeat[row * 512 + tid];
    __syncthreads();
    float s = bi[tid];
    for (int k = 0; k < 512; k++) s = fmaf(cfr[k], Wi[k * 512 + tid], s);
    s = fmaxf(s, 0.0f);
    cf2s[tid] = s;
    g_cf2[row * 512 + tid] = s;
    __syncthreads();
    if (tid < 256) {
        float sa = ba2[tid], sg = bb2[tid];
        for (int k = 0; k < 512; k++) {
            float v = cf2s[k];
            sa = fmaf(v, Wa2[k * 256 + tid], sa);
            sg = fmaf(v, Wb2[k * 256 + tid], sg);
        }
        float a = tanhf(sa);
        float gg = 1.0f / (1.0f + expf(-sg));
        red[tid] = a * gg * Wc2[tid];
    }
    __syncthreads();
    for (int sft = 128; sft > 0; sft >>= 1) {
        if (tid < sft && tid + sft < 256) red[tid] += red[tid + sft];
        __syncthreads();
    }
    if (tid == 0) g_A2[row] = red[0];
}

// =====================================================================
// Per-batch masked softmax over clusters, slide pooling, head MLP
// =====================================================================
__global__ __launch_bounds__(512) void k_final(
    const float* __restrict__ Wint, const float* __restrict__ bint,
    const float* __restrict__ Wcls, const float* __restrict__ bcls,
    float* __restrict__ out)
{
    __shared__ float Wsm[NC];
    __shared__ float slide[512];
    __shared__ float inter[256];
    const int b = blockIdx.x, tid = threadIdx.x;

    if (tid == 0) {
        float av[NC];
        float m = -3.0e38f;
        for (int c = 0; c < NC; c++) {
            av[c] = g_present[b * NC + c] ? g_A2[b * NC + c] : -3.0e38f;
            m = fmaxf(m, av[c]);
        }
        float sden = 0.0f;
        float ex[NC];
        for (int c = 0; c < NC; c++) { ex[c] = expf(av[c] - m); sden += ex[c]; }
        for (int c = 0; c < NC; c++) Wsm[c] = ex[c] / sden;
    }
    __syncthreads();
    float sv = 0.0f;
    for (int c = 0; c < NC; c++) sv = fmaf(Wsm[c], g_cf2[(b * NC + c) * 512 + tid], sv);
    slide[tid] = sv;
    __syncthreads();
    if (tid < 256) {
        float v = bint[tid];
        for (int k = 0; k < 512; k++) v = fmaf(slide[k], Wint[k * 256 + tid], v);
        inter[tid] = fmaxf(v, 0.0f);
    }
    __syncthreads();
    if (tid < 2) {
        float o = bcls[tid];
        for (int k = 0; k < 256; k++) o = fmaf(inter[k], Wcls[k * 2 + tid], o);
        out[b * 2 + tid] = o;
    }
}

// =====================================================================
extern "C" void kernel_launch(void* const* d_in, const int* in_sizes, int n_in,
                              void* d_out, int out_size)
{
    const float* h    = (const float*)d_in[0];
    const int*   cids = (const int*)  d_in[1];
    const float* emb  = (const float*)d_in[2];
    const float* Wf   = (const float*)d_in[3];
    const float* bfu  = (const float*)d_in[4];
    const float* Wa1  = (const float*)d_in[5];
    const float* ba1  = (const float*)d_in[6];
    const float* Wb1  = (const float*)d_in[7];
    const float* bb1  = (const float*)d_in[8];
    const float* Wc1  = (const float*)d_in[9];
    // d_in[10] = bc1: constant shift inside segment softmax -> cancels exactly
    const float* Wi   = (const float*)d_in[11];
    const float* bi   = (const float*)d_in[12];
    const float* Wa2  = (const float*)d_in[13];
    const float* ba2  = (const float*)d_in[14];
    const float* Wb2  = (const float*)d_in[15];
    const float* bb2  = (const float*)d_in[16];
    const float* Wc2  = (const float*)d_in[17];
    // d_in[18] = bc2: cancels in inter-cluster softmax
    const float* Wint = (const float*)d_in[19];
    const float* bint = (const float*)d_in[20];
    const float* Wcls = (const float*)d_in[21];
    const float* bcls = (const float*)d_in[22];
    float* out = (float*)d_out;

    cudaFuncSetAttribute(k_gemm<0>, cudaFuncAttributeMaxDynamicSharedMemorySize, SMEM_REQ);
    cudaFuncSetAttribute(k_gemm<1>, cudaFuncAttributeMaxDynamicSharedMemorySize, SMEM_REQ);

    k_pack_wf <<<512, 256>>>(Wf);
    k_pack_wab<<<512, 256>>>(Wa1, Wb1);
    k_gemm<0> <<<dim3(2, 1024), 512, SMEM_REQ>>>(h, cids, emb, Wf, bfu, nullptr, nullptr, nullptr);
    k_gemm<1> <<<dim3(2, 1024), 512, SMEM_REQ>>>(nullptr, cids, emb, Wf, bfu, ba1, bb1, Wc1);
    k_reduceA <<<(MTOT + 255) / 256, 256>>>();
    k_segpart <<<64, 256>>>(cids);
    k_segfin  <<<1, 128>>>();
    k_segexp  <<<64, 256>>>(cids);
    k_segfin2 <<<1, 128>>>();
    k_w       <<<(MTOT + 255) / 256, 256>>>(cids);
    k_accum   <<<dim3(64, BATCH), 512>>>(cids);
    k_reduceC <<<(NSEG * 512 + 255) / 256, 256>>>();
    k_intra   <<<NSEG, 512>>>(Wi, bi, Wa2, ba2, Wb2, bb2, Wc2);
    k_final   <<<BATCH, 512>>>(Wint, bint, Wcls, bcls, out);
}

// round 17
// speedup vs baseline: 2.2543x; 1.0029x over previous
#include <cuda_runtime.h>
#include <cuda_bf16.h>
#include <math.h>
#include <stdint.h>

// ---------------- problem constants ----------------
#define BATCH 8
#define NTOK  16384
#define MTOT  (BATCH * NTOK)      // 131072 tokens
#define NC    11                  // C+1 clusters
#define NSEG  (BATCH * NC)        // 88

// ---------------- scratch (device globals; no allocations allowed) ----------------
__device__ __nv_bfloat16 g_Xhi[(size_t)MTOT * 512];   // fused features, bf16 hi plane
__device__ __nv_bfloat16 g_Xlo[(size_t)MTOT * 512];   // bf16 lo (residual) plane
__device__ float g_Apart[4 * MTOT];
__device__ float g_A[MTOT];
__device__ float g_w[MTOT];
__device__ float g_pmax[64 * NC];
__device__ int   g_pcnt[64 * NC];
__device__ float g_psum[64 * NC];
__device__ float g_segmax[NSEG];
__device__ float g_segden[NSEG];
__device__ int   g_present[NSEG];
__device__ float g_cfeatPart[BATCH * 64 * NC * 512];
__device__ float g_cfeat[NSEG * 512];
__device__ float g_cf2[NSEG * 512];
__device__ float g_A2[NSEG];
// prepacked weights, K-major [N=512 rows][K=512], hi/lo bf16 split
__device__ __nv_bfloat16 g_Bf_hi[512 * 512];
__device__ __nv_bfloat16 g_Bf_lo[512 * 512];
__device__ __nv_bfloat16 g_Bab_hi[512 * 512];
__device__ __nv_bfloat16 g_Bab_lo[512 * 512];

__device__ __forceinline__ int clip_cid(int c) { return c < 0 ? 0 : (c > 10 ? 10 : c); }

__device__ __forceinline__ uint32_t smu(const void* p) {
    return (uint32_t)__cvta_generic_to_shared(p);
}

// ---------------- sm_90-baseline PTX helpers (valid at .target sm_103) ----------
#define CP_ASYNC16(dst, src) \
    asm volatile("cp.async.cg.shared.global [%0], [%1], 16;" :: "r"(dst), "l"(src))
#define CP_COMMIT() asm volatile("cp.async.commit_group;")
#define CP_WAIT0()  asm volatile("cp.async.wait_group 0;" ::: "memory")

__device__ __forceinline__ void ldsm4(uint32_t* r, uint32_t addr) {
    asm volatile("ldmatrix.sync.aligned.m8n8.x4.shared.b16 {%0,%1,%2,%3}, [%4];"
        : "=r"(r[0]), "=r"(r[1]), "=r"(r[2]), "=r"(r[3]) : "r"(addr));
}
__device__ __forceinline__ void mma4(float* d, const uint32_t* a, const uint32_t* b) {
    asm volatile(
        "mma.sync.aligned.m16n8k16.row.col.f32.bf16.bf16.f32 "
        "{%0,%1,%2,%3}, {%4,%5,%6,%7}, {%8,%9}, {%0,%1,%2,%3};"
        : "+f"(d[0]), "+f"(d[1]), "+f"(d[2]), "+f"(d[3])
        : "r"(a[0]), "r"(a[1]), "r"(a[2]), "r"(a[3]), "r"(b[0]), "r"(b[1]));
}

__device__ __forceinline__ void split2(float a, float b, uint32_t& hi, uint32_t& lo) {
    __nv_bfloat162 hp = __floats2bfloat162_rn(a, b);
    float ra = a - __low2float(hp);
    float rb = b - __high2float(hp);
    __nv_bfloat162 lp = __floats2bfloat162_rn(ra, rb);
    hi = *reinterpret_cast<uint32_t*>(&hp);
    lo = *reinterpret_cast<uint32_t*>(&lp);
}

// ---------------- GEMM tiling ----------------
// BM=128, BN=128, BK=32. 256 threads = 8 warps (2 m x 4 n), warp tile 64x32.
// 2 CTAs/SM: sibling CTA's HMMA covers this CTA's barrier/LDSM latency.
// Rows padded to 80B (20 words): 8-row ldmatrix phases conflict-free (R13-proven).
#define RSB 80                         // row stride bytes (64 B data + 16 pad)
#define ST_AHI 0
#define ST_ALO 10240                   // 128*80
#define ST_BHI 20480
#define ST_BLO 30720
#define STAGE  40960
#define NKIT   16                      // 512 / 32
#define OFF_EPI  81920                 // 2*STAGE
#define OFF_SRED (OFF_EPI + 4608)      // epi max 1152 floats (EPI=0)
#define SMEM_REQ 89088                 // + 2560 sred

// =====================================================================
// HMMA GEMM. EPI=0: fuse (h -> X hi/lo planes, bias+emb-tail+relu)
//            EPI=1: gate (X -> tanh*sigmoid dot Wc1 per-token partials)
// 3-term bf16 split: AhiBhi + AloBhi + AhiBlo.
// =====================================================================
template <int EPI>
__global__ __launch_bounds__(256, 2) void k_gemm(
    const float* __restrict__ hsrc, const int* __restrict__ cids,
    const float* __restrict__ emb, const float* __restrict__ Wf,
    const float* __restrict__ bfu, const float* __restrict__ ba1,
    const float* __restrict__ bb1, const float* __restrict__ Wc1)
{
    extern __shared__ __align__(16) char dsm[];
    const int tid = threadIdx.x;
    const int lane = tid & 31, wid = tid >> 5;
    const int wm = wid >> 2, wn = wid & 3;
    const int colBase = blockIdx.x * 128;
    const int rowBase = blockIdx.y * 128;

    // ---- epilogue constants ----
    float* epi = (float*)(dsm + OFF_EPI);
    if (EPI == 0) {
        if (tid < 128) epi[tid] = bfu[colBase + tid];
        for (int i = tid; i < 1024; i += 256)
            epi[128 + i] = Wf[(512 + (i >> 7)) * 512 + colBase + (i & 127)];
    } else {
        if (tid < 64) {
            epi[tid]       = ba1[colBase / 2 + tid];
            epi[64 + tid]  = bb1[colBase / 2 + tid];
            epi[128 + tid] = Wc1[colBase / 2 + tid];
        }
    }

    // ---- per-thread loader indices ----
    const __nv_bfloat16* Bh0 = (EPI == 0) ? g_Bf_hi : g_Bab_hi;
    const __nv_bfloat16* Bl0 = (EPI == 0) ? g_Bf_lo : g_Bab_lo;
    const uint32_t smBase = smu(dsm);

    // B: per plane 128 rows x 4 chunks(16B) = 512; 2 chunks/thread (both planes)
    const char* srcBh[2]; const char* srcBl[2]; uint32_t dstB[2];
#pragma unroll
    for (int i = 0; i < 2; i++) {
        int c = tid + 256 * i;
        int rB = c >> 2, hB = c & 3;
        srcBh[i] = (const char*)(Bh0 + (size_t)(colBase + rB) * 512) + hB * 16;
        srcBl[i] = (const char*)(Bl0 + (size_t)(colBase + rB) * 512) + hB * 16;
        dstB[i] = rB * RSB + hB * 16;
    }

    // GEMM1 A loader (fp32 h, runtime split): 16 floats/thread
    const int rA1 = tid >> 1, half1 = tid & 1;
    const float* srcA1 = (EPI == 0) ? (hsrc + (size_t)(rowBase + rA1) * 512 + half1 * 16) : nullptr;
    const uint32_t dstA1off = rA1 * RSB + half1 * 32;
    // GEMM2 A loader (pre-split planes): 128 rows x 4 chunks; 2/thread
    const char* srcA2h[2]; const char* srcA2l[2]; uint32_t dstA2[2];
#pragma unroll
    for (int i = 0; i < 2; i++) {
        int c = tid + 256 * i;
        int rr = c >> 2, hh = c & 3;
        srcA2h[i] = (const char*)(g_Xhi + (size_t)(rowBase + rr) * 512) + hh * 16;
        srcA2l[i] = (const char*)(g_Xlo + (size_t)(rowBase + rr) * 512) + hh * 16;
        dstA2[i] = rr * RSB + hh * 16;
    }

    // ---- ldmatrix addresses (per thread; +kk*32 B selects k-half) ----
    uint32_t offA[4], offB[2];
    {
        int rowAf = wm * 64 + (lane & 15);
        int kAf = (lane >> 4) * 8;
#pragma unroll
        for (int mt = 0; mt < 4; mt++) offA[mt] = (rowAf + mt * 16) * RSB + kAf * 2;
        int rowBf = wn * 32 + (lane & 7) + 8 * (lane >> 4);
        int kBf = ((lane >> 3) & 1) * 8;
#pragma unroll
        for (int nf2 = 0; nf2 < 2; nf2++) offB[nf2] = (rowBf + nf2 * 16) * RSB + kBf * 2;
    }

    // ---- stage loader (cp.async part); bo = ks*64 bytes (32 bf16) ----
    auto load_stage = [&](int sbuf, int ks) {
        uint32_t db = smBase + sbuf * STAGE;
        int bo = ks * 64;
#pragma unroll
        for (int i = 0; i < 2; i++) {
            CP_ASYNC16(db + ST_BHI + dstB[i], srcBh[i] + bo);
            CP_ASYNC16(db + ST_BLO + dstB[i], srcBl[i] + bo);
        }
        if (EPI != 0) {
#pragma unroll
            for (int i = 0; i < 2; i++) {
                CP_ASYNC16(db + ST_AHI + dstA2[i], srcA2h[i] + bo);
                CP_ASYNC16(db + ST_ALO + dstA2[i], srcA2l[i] + bo);
            }
        }
        CP_COMMIT();
    };
    // EPI==0: fp32 A split-store (16 floats) into stage sbuf
    auto store_A1 = [&](int sbuf, const float4* v) {
        uint32_t h[8], l[8];
#pragma unroll
        for (int q = 0; q < 4; q++) {
            split2(v[q].x, v[q].y, h[2 * q], l[2 * q]);
            split2(v[q].z, v[q].w, h[2 * q + 1], l[2 * q + 1]);
        }
        char* dc = dsm + sbuf * STAGE;
        *(uint4*)(dc + ST_AHI + dstA1off)      = make_uint4(h[0], h[1], h[2], h[3]);
        *(uint4*)(dc + ST_AHI + dstA1off + 16) = make_uint4(h[4], h[5], h[6], h[7]);
        *(uint4*)(dc + ST_ALO + dstA1off)      = make_uint4(l[0], l[1], l[2], l[3]);
        *(uint4*)(dc + ST_ALO + dstA1off + 16) = make_uint4(l[4], l[5], l[6], l[7]);
    };

    // ---- preamble: stage 0 ----
    {
        load_stage(0, 0);
        if (EPI == 0) {
            float4 v[4];
#pragma unroll
            for (int q = 0; q < 4; q++) v[q] = *(const float4*)(srcA1 + q * 4);
            store_A1(0, v);
        }
        CP_WAIT0();
    }
    __syncthreads();

    float acc[4][4][4];
#pragma unroll
    for (int i = 0; i < 4; i++)
#pragma unroll
        for (int j = 0; j < 4; j++)
#pragma unroll
            for (int k = 0; k < 4; k++) acc[i][j][k] = 0.0f;

    // ---- main loop: 16 k-iters of BK=32, double buffered ----
    int buf = 0;
#pragma unroll 1
    for (int ks = 0; ks < NKIT; ks++) {
        float4 av[4];
        if (ks < NKIT - 1) {
            load_stage(buf ^ 1, ks + 1);
            if (EPI == 0) {
#pragma unroll
                for (int q = 0; q < 4; q++)
                    av[q] = *(const float4*)(srcA1 + (ks + 1) * 32 + q * 4);
            }
        }

        // compute on buf (stage ks): two BK=16 sub-steps
        const uint32_t sb = smBase + buf * STAGE;
#pragma unroll
        for (int kk = 0; kk < 2; kk++) {
            const uint32_t ko = kk * 32;   // 16 bf16 = 32 bytes
            uint32_t ah[4][4], al[4][4];
#pragma unroll
            for (int mt = 0; mt < 4; mt++) {
                ldsm4(ah[mt], sb + ST_AHI + offA[mt] + ko);
                ldsm4(al[mt], sb + ST_ALO + offA[mt] + ko);
            }
#pragma unroll
            for (int nf2 = 0; nf2 < 2; nf2++) {
                uint32_t bh[4], bl[4];
                ldsm4(bh, sb + ST_BHI + offB[nf2] + ko);
#pragma unroll
                for (int mt = 0; mt < 4; mt++) {
                    mma4(acc[mt][2 * nf2], ah[mt], bh);
                    mma4(acc[mt][2 * nf2 + 1], ah[mt], bh + 2);
                }
#pragma unroll
                for (int mt = 0; mt < 4; mt++) {
                    mma4(acc[mt][2 * nf2], al[mt], bh);
                    mma4(acc[mt][2 * nf2 + 1], al[mt], bh + 2);
                }
                ldsm4(bl, sb + ST_BLO + offB[nf2] + ko);
#pragma unroll
                for (int mt = 0; mt < 4; mt++) {
                    mma4(acc[mt][2 * nf2], ah[mt], bl);
                    mma4(acc[mt][2 * nf2 + 1], ah[mt], bl + 2);
                }
            }
        }

        if (ks < NKIT - 1) {
            if (EPI == 0) store_A1(buf ^ 1, av);
            CP_WAIT0();
            __syncthreads();
        }
        buf ^= 1;
    }

    // ---- epilogue ----
    const int q = lane >> 2, p = lane & 3;
    if (EPI == 0) {
#pragma unroll
        for (int mt = 0; mt < 4; mt++)
#pragma unroll
            for (int half = 0; half < 2; half++) {
                int r = rowBase + wm * 64 + mt * 16 + q + 8 * half;
                int cid = clip_cid(cids[r]);
                float ev[8];
#pragma unroll
                for (int e = 0; e < 8; e++) ev[e] = emb[cid * 8 + e];
#pragma unroll
                for (int nf = 0; nf < 4; nf++) {
                    int cl = wn * 32 + nf * 8 + 2 * p;
                    float v0 = acc[mt][nf][2 * half]     + epi[cl];
                    float v1 = acc[mt][nf][2 * half + 1] + epi[cl + 1];
#pragma unroll
                    for (int e = 0; e < 8; e++) {
                        v0 = fmaf(ev[e], epi[128 + e * 128 + cl], v0);
                        v1 = fmaf(ev[e], epi[128 + e * 128 + cl + 1], v1);
                    }
                    v0 = fmaxf(v0, 0.0f);
                    v1 = fmaxf(v1, 0.0f);
                    uint32_t hi, lo;
                    split2(v0, v1, hi, lo);
                    size_t go = (size_t)r * 512 + colBase + cl;
                    *reinterpret_cast<uint32_t*>(g_Xhi + go) = hi;
                    *reinterpret_cast<uint32_t*>(g_Xlo + go) = lo;
                }
            }
    } else {
        float* sred = (float*)(dsm + OFF_SRED);
#pragma unroll
        for (int mt = 0; mt < 4; mt++)
#pragma unroll
            for (int half = 0; half < 2; half++) {
                float s = 0.0f;
#pragma unroll
                for (int nf = 0; nf < 4; nf++) {
                    int jl = wn * 16 + nf * 4 + p;
                    float va = acc[mt][nf][2 * half]     + epi[jl];
                    float vg = acc[mt][nf][2 * half + 1] + epi[64 + jl];
                    float a = tanhf(va);
                    float gg = 1.0f / (1.0f + expf(-vg));
                    s = fmaf(a * gg, epi[128 + jl], s);
                }
                s += __shfl_xor_sync(0xFFFFFFFFu, s, 1);
                s += __shfl_xor_sync(0xFFFFFFFFu, s, 2);
                if (p == 0)
                    sred[(wm * 64 + mt * 16 + q + 8 * half) * 5 + wn] = s;
            }
        __syncthreads();
        if (tid < 128) {
            float t = sred[tid * 5] + sred[tid * 5 + 1] + sred[tid * 5 + 2] + sred[tid * 5 + 3];
            g_Apart[(size_t)blockIdx.x * MTOT + rowBase + tid] = t;
        }
    }
}

// =====================================================================
// Weight prepack: fp32 [K,N] -> bf16 hi/lo K-major [N,K]
// =====================================================================
__global__ __launch_bounds__(256) void k_pack_wf(const float* __restrict__ Wf) {
    int n = blockIdx.x;
    for (int k = threadIdx.x; k < 512; k += 256) {
        float x = Wf[k * 512 + n];
        __nv_bfloat16 hi = __float2bfloat16(x);
        __nv_bfloat16 lo = __float2bfloat16(x - __bfloat162float(hi));
        g_Bf_hi[n * 512 + k] = hi;
        g_Bf_lo[n * 512 + k] = lo;
    }
}
// interleave: row 2p = Wa1 col p, row 2p+1 = Wb1 col p
__global__ __launch_bounds__(256) void k_pack_wab(const float* __restrict__ Wa1,
                                                  const float* __restrict__ Wb1) {
    int n = blockIdx.x;
    int p = n >> 1;
    const float* src = (n & 1) ? Wb1 : Wa1;
    for (int k = threadIdx.x; k < 512; k += 256) {
        float x = src[k * 256 + p];
        __nv_bfloat16 hi = __float2bfloat16(x);
        __nv_bfloat16 lo = __float2bfloat16(x - __bfloat162float(hi));
        g_Bab_hi[n * 512 + k] = hi;
        g_Bab_lo[n * 512 + k] = lo;
    }
}

__global__ void k_reduceA() {
    int t = blockIdx.x * blockDim.x + threadIdx.x;
    if (t >= MTOT) return;
    float s = 0.0f;
#pragma unroll
    for (int j = 0; j < 4; j++) s += g_Apart[(size_t)j * MTOT + t];
    g_A[t] = s;
}

// =====================================================================
// Segment stats: 64-way partials (8 chunks x 8 batches), then tiny combines
// =====================================================================
__global__ __launch_bounds__(256) void k_segpart(const int* __restrict__ cids) {
    __shared__ float sm[NC * 256];
    __shared__ int   sc[NC * 256];
    const int blk = blockIdx.x, b = blk >> 3, ch = blk & 7, tid = threadIdx.x;
    for (int c = 0; c < NC; c++) { sm[c * 256 + tid] = -3.0e38f; sc[c * 256 + tid] = 0; }
    const int base = b * NTOK + ch * 2048;
    for (int it = 0; it < 8; it++) {
        int t = base + it * 256 + tid;
        int c = clip_cid(cids[t]);
        float v = g_A[t];
        if (v > sm[c * 256 + tid]) sm[c * 256 + tid] = v;
        sc[c * 256 + tid]++;
    }
    __syncthreads();
    if (tid < NC) {
        float m = -3.0e38f; int cnt = 0;
        for (int i = 0; i < 256; i++) { m = fmaxf(m, sm[tid * 256 + i]); cnt += sc[tid * 256 + i]; }
        g_pmax[blk * NC + tid] = m;
        g_pcnt[blk * NC + tid] = cnt;
    }
}
__global__ void k_segfin() {
    int s = threadIdx.x;
    if (s >= NSEG) return;
    int b = s / NC, c = s % NC;
    float m = -3.0e38f; int cnt = 0;
    for (int ch = 0; ch < 8; ch++) {
        m = fmaxf(m, g_pmax[(b * 8 + ch) * NC + c]);
        cnt += g_pcnt[(b * 8 + ch) * NC + c];
    }
    g_segmax[s] = (cnt > 0) ? m : 0.0f;
    g_present[s] = (cnt > 0) ? 1 : 0;
}
__global__ __launch_bounds__(256) void k_segexp(const int* __restrict__ cids) {
    __shared__ float sm[NC * 256];
    __shared__ float fm[NC];
    const int blk = blockIdx.x, b = blk >> 3, ch = blk & 7, tid = threadIdx.x;
    if (tid < NC) fm[tid] = g_segmax[b * NC + tid];
    for (int c = 0; c < NC; c++) sm[c * 256 + tid] = 0.0f;
    __syncthreads();
    const int base = b * NTOK + ch * 2048;
    for (int it = 0; it < 8; it++) {
        int t = base + it * 256 + tid;
        int c = clip_cid(cids[t]);
        sm[c * 256 + tid] += expf(g_A[t] - fm[c]);
    }
    __syncthreads();
    if (tid < NC) {
        float s = 0.0f;
        for (int i = 0; i < 256; i++) s += sm[tid * 256 + i];
        g_psum[blk * NC + tid] = s;
    }
}
__global__ void k_segfin2() {
    int s = threadIdx.x;
    if (s >= NSEG) return;
    int b = s / NC, c = s % NC;
    float d = 0.0f;
    for (int ch = 0; ch < 8; ch++) d += g_psum[(b * 8 + ch) * NC + c];
    g_segden[s] = d;
}
__global__ void k_w(const int* __restrict__ cids) {
    int t = blockIdx.x * blockDim.x + threadIdx.x;
    if (t >= MTOT) return;
    int b = t >> 14;
    int c = clip_cid(cids[t]);
    g_w[t] = expf(g_A[t] - g_segmax[b * NC + c]) / g_segden[b * NC + c];
}

// =====================================================================
// Segment-sum of w-weighted X (hi+lo reconstruct), deterministic partials
// 64 chunks x 8 batches (512 blocks) for better SM coverage
// =====================================================================
__global__ __launch_bounds__(512) void k_accum(const int* __restrict__ cids) {
    __shared__ float acc[NC * 512];
    const int chunk = blockIdx.x, b = blockIdx.y, tid = threadIdx.x;
    for (int i = tid; i < NC * 512; i += 512) acc[i] = 0.0f;
    __syncthreads();
    const int base = b * NTOK + chunk * 256;
    for (int it = 0; it < 256; it++) {
        int row = base + it;
        int c = clip_cid(cids[row]);
        float wv = g_w[row];
        size_t off = (size_t)row * 512 + tid;
        float x = __bfloat162float(g_Xhi[off]) + __bfloat162float(g_Xlo[off]);
        acc[c * 512 + tid] += x * wv;
    }
    __syncthreads();
    float* dst = &g_cfeatPart[(size_t)(b * 64 + chunk) * NC * 512];
    for (int c = 0; c < NC; c++) dst[c * 512 + tid] = acc[c * 512 + tid];
}
__global__ void k_reduceC() {
    int idx = blockIdx.x * blockDim.x + threadIdx.x;
    if (idx >= NSEG * 512) return;
    int b = idx / (NC * 512);
    int off = idx % (NC * 512);
    float s = 0.0f;
#pragma unroll
    for (int j = 0; j < 64; j++) s += g_cfeatPart[(size_t)(b * 64 + j) * NC * 512 + off];
    g_cfeat[idx] = s;
}

// =====================================================================
// Per-cluster-row MLP + gated attention-2 logit (88 rows)
// =====================================================================
__global__ __launch_bounds__(512) void k_intra(
    const float* __restrict__ Wi, const float* __restrict__ bi,
    const float* __restrict__ Wa2, const float* __restrict__ ba2,
    const float* __restrict__ Wb2, const float* __restrict__ bb2,
    const float* __restrict__ Wc2)
{
    __shared__ float cfr[512];
    __shared__ float cf2s[512];
    __shared__ float red[256];
    const int row = blockIdx.x, tid = threadIdx.x;

    cfr[tid] = g_cfeat[row * 512 + tid];
    __syncthreads();
    float s = bi[tid];
    for (int k = 0; k < 512; k++) s = fmaf(cfr[k], Wi[k * 512 + tid], s);
    s = fmaxf(s, 0.0f);
    cf2s[tid] = s;
    g_cf2[row * 512 + tid] = s;
    __syncthreads();
    if (tid < 256) {
        float sa = ba2[tid], sg = bb2[tid];
        for (int k = 0; k < 512; k++) {
            float v = cf2s[k];
            sa = fmaf(v, Wa2[k * 256 + tid], sa);
            sg = fmaf(v, Wb2[k * 256 + tid], sg);
        }
        float a = tanhf(sa);
        float gg = 1.0f / (1.0f + expf(-sg));
        red[tid] = a * gg * Wc2[tid];
    }
    __syncthreads();
    for (int sft = 128; sft > 0; sft >>= 1) {
        if (tid < sft && tid + sft < 256) red[tid] += red[tid + sft];
        __syncthreads();
    }
    if (tid == 0) g_A2[row] = red[0];
}

// =====================================================================
// Per-batch masked softmax over clusters, slide pooling, head MLP
// =====================================================================
__global__ __launch_bounds__(512) void k_final(
    const float* __restrict__ Wint, const float* __restrict__ bint,
    const float* __restrict__ Wcls, const float* __restrict__ bcls,
    float* __restrict__ out)
{
    __shared__ float Wsm[NC];
    __shared__ float slide[512];
    __shared__ float inter[256];
    const int b = blockIdx.x, tid = threadIdx.x;

    if (tid == 0) {
        float av[NC];
        float m = -3.0e38f;
        for (int c = 0; c < NC; c++) {
            av[c] = g_present[b * NC + c] ? g_A2[b * NC + c] : -3.0e38f;
            m = fmaxf(m, av[c]);
        }
        float sden = 0.0f;
        float ex[NC];
        for (int c = 0; c < NC; c++) { ex[c] = expf(av[c] - m); sden += ex[c]; }
        for (int c = 0; c < NC; c++) Wsm[c] = ex[c] / sden;
    }
    __syncthreads();
    float sv = 0.0f;
    for (int c = 0; c < NC; c++) sv = fmaf(Wsm[c], g_cf2[(b * NC + c) * 512 + tid], sv);
    slide[tid] = sv;
    __syncthreads();
    if (tid < 256) {
        float v = bint[tid];
        for (int k = 0; k < 512; k++) v = fmaf(slide[k], Wint[k * 256 + tid], v);
        inter[tid] = fmaxf(v, 0.0f);
    }
    __syncthreads();
    if (tid < 2) {
        float o = bcls[tid];
        for (int k = 0; k < 256; k++) o = fmaf(inter[k], Wcls[k * 2 + tid], o);
        out[b * 2 + tid] = o;
    }
}

// =====================================================================
extern "C" void kernel_launch(void* const* d_in, const int* in_sizes, int n_in,
                              void* d_out, int out_size)
{
    const float* h    = (const float*)d_in[0];
    const int*   cids = (const int*)  d_in[1];
    const float* emb  = (const float*)d_in[2];
    const float* Wf   = (const float*)d_in[3];
    const float* bfu  = (const float*)d_in[4];
    const float* Wa1  = (const float*)d_in[5];
    const float* ba1  = (const float*)d_in[6];
    const float* Wb1  = (const float*)d_in[7];
    const float* bb1  = (const float*)d_in[8];
    const float* Wc1  = (const float*)d_in[9];
    // d_in[10] = bc1: constant shift inside segment softmax -> cancels exactly
    const float* Wi   = (const float*)d_in[11];
    const float* bi   = (const float*)d_in[12];
    const float* Wa2  = (const float*)d_in[13];
    const float* ba2  = (const float*)d_in[14];
    const float* Wb2  = (const float*)d_in[15];
    const float* bb2  = (const float*)d_in[16];
    const float* Wc2  = (const float*)d_in[17];
    // d_in[18] = bc2: cancels in inter-cluster softmax
    const float* Wint = (const float*)d_in[19];
    const float* bint = (const float*)d_in[20];
    const float* Wcls = (const float*)d_in[21];
    const float* bcls = (const float*)d_in[22];
    float* out = (float*)d_out;

    cudaFuncSetAttribute(k_gemm<0>, cudaFuncAttributeMaxDynamicSharedMemorySize, SMEM_REQ);
    cudaFuncSetAttribute(k_gemm<1>, cudaFuncAttributeMaxDynamicSharedMemorySize, SMEM_REQ);

    k_pack_wf <<<512, 256>>>(Wf);
    k_pack_wab<<<512, 256>>>(Wa1, Wb1);
    k_gemm<0> <<<dim3(4, 1024), 256, SMEM_REQ>>>(h, cids, emb, Wf, bfu, nullptr, nullptr, nullptr);
    k_gemm<1> <<<dim3(4, 1024), 256, SMEM_REQ>>>(nullptr, cids, emb, Wf, bfu, ba1, bb1, Wc1);
    k_reduceA <<<(MTOT + 255) / 256, 256>>>();
    k_segpart <<<64, 256>>>(cids);
    k_segfin  <<<1, 128>>>();
    k_segexp  <<<64, 256>>>(cids);
    k_segfin2 <<<1, 128>>>();
    k_w       <<<(MTOT + 255) / 256, 256>>>(cids);
    k_accum   <<<dim3(64, BATCH), 512>>>(cids);
    k_reduceC <<<(NSEG * 512 + 255) / 256, 256>>>();
    k_intra   <<<NSEG, 512>>>(Wi, bi, Wa2, ba2, Wb2, bb2, Wc2);
    k_final   <<<BATCH, 512>>>(Wint, bint, Wcls, bcls, out);
}